// round 10
// baseline (speedup 1.0000x reference)
#include <cuda_runtime.h>
#include <math.h>

// Problem constants
#define BQ    8
#define TT    1024
#define EMB   1024
#define NH    16
#define DH    64
#define NTOK  (BQ*TT)      // 8192
#define BHD   (BQ*NH)      // 128

#define LOG2E 1.4426950408889634f

// -------- scratch (static device arrays: no allocation APIs allowed) --------
__device__ float g_q [BHD*TT*DH];   // [b,h,t,d]
__device__ float g_k [BHD*TT*DH];
__device__ float g_v [BHD*TT*DH];
__device__ float g_ao[NTOK*EMB];    // attention output [b*t, h*d]

// ---------------------------------------------------------------------------
// helpers
// ---------------------------------------------------------------------------
__device__ __forceinline__ unsigned f2tf(float x) {
    unsigned u;
    asm("cvt.rna.tf32.f32 %0, %1;" : "=r"(u) : "f"(x));
    return u;
}
__device__ __forceinline__ float tff(float x) { return __uint_as_float(f2tf(x)); }

__device__ __forceinline__ void mma8(float* d, const unsigned* a, unsigned b0, unsigned b1) {
    asm volatile(
        "mma.sync.aligned.m16n8k8.row.col.f32.tf32.tf32.f32 "
        "{%0,%1,%2,%3}, {%4,%5,%6,%7}, {%8,%9}, {%0,%1,%2,%3};\n"
        : "+f"(d[0]), "+f"(d[1]), "+f"(d[2]), "+f"(d[3])
        : "r"(a[0]), "r"(a[1]), "r"(a[2]), "r"(a[3]), "r"(b0), "r"(b1));
}

// FMA-only exp2 (no MUFU). y <= 0 expected; clamped below -126 -> ~0.
__device__ __forceinline__ float exp2_fast(float y) {
    y = fmaxf(y, -126.0f);
    float r  = y + 12582912.0f;
    int   n  = __float_as_int(r) - 0x4B400000;
    float f  = y - (r - 12582912.0f);
    float p  =            1.3333558146428443e-3f;
    p = fmaf(p, f,        9.6181291076284771e-3f);
    p = fmaf(p, f,        5.5504108664821580e-2f);
    p = fmaf(p, f,        2.4022650695910072e-1f);
    p = fmaf(p, f,        6.9314718055994531e-1f);
    p = fmaf(p, f,        1.0f);
    return p * __int_as_float((n + 127) << 23);
}

// Blocked smem layout: 8x8 blocks of 64 floats; within a block, k-column k
// lives at slot 2*(k&3)+(k>>2) so pairs (t, t+4) are adjacent -> LDS.64 frags.
// idx(r, k; KBLK) = ((r>>3)*KBLK + (k>>3))*64 + (r&7)*8 + slot(k&7)

// ---------------------------------------------------------------------------
// tf32 GEMM: C[m][n] = sum_k A[m][k]*B[n][k] + bias[n]
// M=8192 N=1024 K=1024. 128x128 tile, BK=32, 256 thr, warp tile 32x64.
// Blocked paired-k smem, LDS.64 fragment loads.
// mode 0: row-major C ; mode 1: scatter into [b,h,t,d]
// ---------------------------------------------------------------------------
__global__ __launch_bounds__(256, 2)
void gemm_tf32(const float* __restrict__ A, const float* __restrict__ B,
               const float* __restrict__ bias, float* __restrict__ C, int mode)
{
    __shared__ float As[4096];   // 128 rows x 32 k, blocked
    __shared__ float Bs[4096];

    const int tid  = threadIdx.x;
    const int lane = tid & 31, wid = tid >> 5;
    const int g = lane >> 2, t = lane & 3;
    const int wm = (wid >> 1) * 32, wn = (wid & 1) * 64;
    const int m0 = blockIdx.y * 128, n0 = blockIdx.x * 128;

    const int lblk   = ((tid >> 2) & 7) >> 1;
    const int lsub   = (tid >> 2) & 1;
    const int lk0    = (lblk << 3) + (lsub << 1);
    const int lrbase = (tid & 3) + ((tid >> 5) << 2);
    const int lsts   = ((lrbase & 7) << 3) + (lsub << 2);

    float acc[2][8][4];
#pragma unroll
    for (int mt = 0; mt < 2; mt++)
#pragma unroll
        for (int nt = 0; nt < 8; nt++)
#pragma unroll
            for (int c = 0; c < 4; c++) acc[mt][nt][c] = 0.f;

    for (int kb = 0; kb < 1024; kb += 32) {
        __syncthreads();
#pragma unroll
        for (int it = 0; it < 4; it++) {
            int row = lrbase + (it << 5);
            const float* pa = A + (size_t)(m0 + row) * 1024 + kb + lk0;
            const float* pb = B + (size_t)(n0 + row) * 1024 + kb + lk0;
            float2 la = *(const float2*)pa;
            float2 ha = *(const float2*)(pa + 4);
            float2 lb = *(const float2*)pb;
            float2 hb = *(const float2*)(pb + 4);
            int idx = (((row >> 3) << 2) + lblk) * 64 + lsts;
            *(float4*)&As[idx] = make_float4(tff(la.x), tff(ha.x), tff(la.y), tff(ha.y));
            *(float4*)&Bs[idx] = make_float4(tff(lb.x), tff(hb.x), tff(lb.y), tff(hb.y));
        }
        __syncthreads();

#pragma unroll
        for (int kblk = 0; kblk < 4; kblk++) {
            unsigned aF[2][4];
#pragma unroll
            for (int mt = 0; mt < 2; mt++) {
                int rb = (wm >> 3) + 2 * mt;
                float2 lo = *(const float2*)&As[((rb << 2) + kblk) * 64 + (g << 3) + (t << 1)];
                float2 hi = *(const float2*)&As[(((rb + 1) << 2) + kblk) * 64 + (g << 3) + (t << 1)];
                aF[mt][0] = __float_as_uint(lo.x); aF[mt][1] = __float_as_uint(hi.x);
                aF[mt][2] = __float_as_uint(lo.y); aF[mt][3] = __float_as_uint(hi.y);
            }
#pragma unroll
            for (int nt = 0; nt < 8; nt++) {
                int cb = (wn >> 3) + nt;
                float2 bb = *(const float2*)&Bs[((cb << 2) + kblk) * 64 + (g << 3) + (t << 1)];
                unsigned b0 = __float_as_uint(bb.x), b1 = __float_as_uint(bb.y);
                mma8(acc[0][nt], aF[0], b0, b1);
                mma8(acc[1][nt], aF[1], b0, b1);
            }
        }
    }

#pragma unroll
    for (int nt = 0; nt < 8; nt++) {
        int n = n0 + wn + nt * 8 + 2 * t;
        float bv0 = bias[n], bv1 = bias[n + 1];
#pragma unroll
        for (int mt = 0; mt < 2; mt++) {
            int r = m0 + wm + mt * 16 + g;
            float2 v0 = make_float2(acc[mt][nt][0] + bv0, acc[mt][nt][1] + bv1);
            float2 v1 = make_float2(acc[mt][nt][2] + bv0, acc[mt][nt][3] + bv1);
            if (mode == 0) {
                *(float2*)&C[(size_t)r * 1024 + n]       = v0;
                *(float2*)&C[(size_t)(r + 8) * 1024 + n] = v1;
            } else {
                int h = n >> 6, d = n & 63;
                int bb = r >> 10, tq = r & 1023;
                *(float2*)&C[(size_t)((bb * NH + h) * TT + tq) * DH + d]     = v0;
                *(float2*)&C[(size_t)((bb * NH + h) * TT + tq + 8) * DH + d] = v1;
            }
        }
    }
}

// ---------------------------------------------------------------------------
// Flash attention, tf32 MMA. BM=128, BN=64, Dh=64. 128 thr / 4 warps;
// warp w owns rows [32w, 32w+32) exclusively (2 m16 tiles) -> quad-local
// softmax. Blocked paired-k smem for Q/K/V (LDS.64 frags); P plain stride-68.
// ---------------------------------------------------------------------------
#define PST 68
#define FLASH_SMEM ((8192 + 4096 + 4096 + 128*PST) * 4)   // 100352 B

__global__ __launch_bounds__(128, 2)
void flash_tf32(const float* __restrict__ amask, const unsigned char* __restrict__ kpm)
{
    extern __shared__ float sm[];
    float* Qs = sm;            // 128x64 blocked (8 kblk)
    float* Ks = Qs + 8192;     // 64x64 blocked
    float* Vs = Ks + 4096;     // 64x64 blocked, row=d, k=token
    float* Ps = Vs + 4096;     // 128x68 plain

    const int tid  = threadIdx.x;
    const int lane = tid & 31, wid = tid >> 5;   // wid 0..3
    const int g = lane >> 2, t = lane & 3;
    const int bh = blockIdx.x, b = bh >> 4, h = bh & 15;
    const int m0 = blockIdx.y * 128;

    const float* Qg = g_q + ((size_t)bh * TT + m0) * DH;
    const float* Kg = g_k + (size_t)bh * TT * DH;
    const float* Vg = g_v + (size_t)bh * TT * DH;

    // ---- load Q tile into blocked layout (once) ----
#pragma unroll
    for (int p = 0; p < 16; p++) {
        int lin = tid + (p << 7);            // 0..2047
        int row = lin >> 4, fc = (lin & 15) << 2;
        float4 q = *(const float4*)(Qg + row * 64 + fc);
        int base = (((row >> 3) << 3) + (fc >> 3)) * 64 + ((row & 7) << 3);
        int s0 = (fc >> 2) & 1;
        Qs[base + s0]     = tff(q.x);
        Qs[base + s0 + 2] = tff(q.y);
        Qs[base + s0 + 4] = tff(q.z);
        Qs[base + s0 + 6] = tff(q.w);
    }

    float o[2][8][4];
#pragma unroll
    for (int mt = 0; mt < 2; mt++)
#pragma unroll
        for (int dt = 0; dt < 8; dt++)
#pragma unroll
            for (int c = 0; c < 4; c++) o[mt][dt][c] = 0.f;

    float mrow[2][2], lrow[2][2];
#pragma unroll
    for (int mt = 0; mt < 2; mt++) {
        mrow[mt][0] = mrow[mt][1] = -1e30f;
        lrow[mt][0] = lrow[mt][1] = 0.f;
    }

    const float SC2 = 0.125f * LOG2E;

    for (int n0k = 0; n0k < TT; n0k += 64) {
        __syncthreads();   // prior iter done reading Ks/Vs

        // ---- fill K (row=token, k=d), paired loads -> STS.128 ----
#pragma unroll
        for (int it = 0; it < 8; it++) {
            int bs  = ((it & 1) << 3) | ((tid >> 2) & 7);
            int row = (tid & 3) | (((tid >> 5) & 3) << 2) | ((it >> 1) << 4);
            int blk = bs >> 1, sub = bs & 1;
            const float* src = Kg + (size_t)(n0k + row) * 64 + (blk << 3) + (sub << 1);
            float2 lo = *(const float2*)src;
            float2 hi = *(const float2*)(src + 4);
            *(float4*)&Ks[(((row >> 3) << 3) + blk) * 64 + ((row & 7) << 3) + (sub << 2)]
                = make_float4(tff(lo.x), tff(hi.x), tff(lo.y), tff(hi.y));
        }
        // ---- fill V transposed (row=d, k=token) ----
#pragma unroll
        for (int it = 0; it < 8; it++) {
            int d   = (tid & 31) | ((it & 1) << 5);
            int bs  = ((tid >> 5) & 3) | ((it >> 1) << 2);
            int blk = bs >> 1, sub = bs & 1;
            int tok = (blk << 3) + (sub << 1);
            const float* src = Vg + (size_t)(n0k + tok) * 64 + d;
            float v0 = src[0], v1 = src[64], v4 = src[4 * 64], v5 = src[5 * 64];
            *(float4*)&Vs[(((d >> 3) << 3) + blk) * 64 + ((d & 7) << 3) + (sub << 2)]
                = make_float4(tff(v0), tff(v4), tff(v1), tff(v5));
        }
        __syncthreads();

        // ---- S = Q @ K^T ----
        float s[2][8][4];
#pragma unroll
        for (int mt = 0; mt < 2; mt++)
#pragma unroll
            for (int nt = 0; nt < 8; nt++)
#pragma unroll
                for (int c = 0; c < 4; c++) s[mt][nt][c] = 0.f;

#pragma unroll
        for (int kblk = 0; kblk < 8; kblk++) {
            unsigned aF[2][4];
#pragma unroll
            for (int mt = 0; mt < 2; mt++) {
                int rb = (wid << 2) + (mt << 1);
                float2 lo = *(const float2*)&Qs[((rb << 3) + kblk) * 64 + (g << 3) + (t << 1)];
                float2 hi = *(const float2*)&Qs[(((rb + 1) << 3) + kblk) * 64 + (g << 3) + (t << 1)];
                aF[mt][0] = __float_as_uint(lo.x); aF[mt][1] = __float_as_uint(hi.x);
                aF[mt][2] = __float_as_uint(lo.y); aF[mt][3] = __float_as_uint(hi.y);
            }
#pragma unroll
            for (int nt = 0; nt < 8; nt++) {
                float2 bb = *(const float2*)&Ks[((nt << 3) + kblk) * 64 + (g << 3) + (t << 1)];
                unsigned b0 = __float_as_uint(bb.x), b1 = __float_as_uint(bb.y);
                mma8(s[0][nt], aF[0], b0, b1);
                mma8(s[1][nt], aF[1], b0, b1);
            }
        }

        // ---- scale + masks (base-2 domain) ----
#pragma unroll
        for (int nt = 0; nt < 8; nt++) {
            int col = n0k + (nt << 3) + (t << 1);
            const unsigned char* kp = kpm + (b << 10) + col;
            float k0 = kp[0] ? -1e30f : 0.f;
            float k1 = kp[1] ? -1e30f : 0.f;
#pragma unroll
            for (int mt = 0; mt < 2; mt++) {
                int r = m0 + (wid << 5) + (mt << 4) + g;
                float2 ma0 = *(const float2*)(amask + (size_t)r * TT + col);
                float2 ma1 = *(const float2*)(amask + (size_t)(r + 8) * TT + col);
                s[mt][nt][0] = fmaf(s[mt][nt][0], SC2, fmaf(ma0.x, LOG2E, k0));
                s[mt][nt][1] = fmaf(s[mt][nt][1], SC2, fmaf(ma0.y, LOG2E, k1));
                s[mt][nt][2] = fmaf(s[mt][nt][2], SC2, fmaf(ma1.x, LOG2E, k0));
                s[mt][nt][3] = fmaf(s[mt][nt][3], SC2, fmaf(ma1.y, LOG2E, k1));
            }
        }

        // ---- online softmax (per mt: rows g and g+8) ----
#pragma unroll
        for (int mt = 0; mt < 2; mt++) {
            float mx0 = -1e30f, mx1 = -1e30f;
#pragma unroll
            for (int nt = 0; nt < 8; nt++) {
                mx0 = fmaxf(mx0, fmaxf(s[mt][nt][0], s[mt][nt][1]));
                mx1 = fmaxf(mx1, fmaxf(s[mt][nt][2], s[mt][nt][3]));
            }
            mx0 = fmaxf(mx0, __shfl_xor_sync(0xffffffffu, mx0, 1));
            mx0 = fmaxf(mx0, __shfl_xor_sync(0xffffffffu, mx0, 2));
            mx1 = fmaxf(mx1, __shfl_xor_sync(0xffffffffu, mx1, 1));
            mx1 = fmaxf(mx1, __shfl_xor_sync(0xffffffffu, mx1, 2));

            float mn0 = fmaxf(mrow[mt][0], mx0), mn1 = fmaxf(mrow[mt][1], mx1);
            float al0 = exp2_fast(mrow[mt][0] - mn0), al1 = exp2_fast(mrow[mt][1] - mn1);
            mrow[mt][0] = mn0; mrow[mt][1] = mn1;

            float rs0 = 0.f, rs1 = 0.f;
#pragma unroll
            for (int nt = 0; nt < 8; nt++) {
                s[mt][nt][0] = exp2_fast(s[mt][nt][0] - mn0);
                s[mt][nt][1] = exp2_fast(s[mt][nt][1] - mn0);
                s[mt][nt][2] = exp2_fast(s[mt][nt][2] - mn1);
                s[mt][nt][3] = exp2_fast(s[mt][nt][3] - mn1);
                rs0 += s[mt][nt][0] + s[mt][nt][1];
                rs1 += s[mt][nt][2] + s[mt][nt][3];
            }
            rs0 += __shfl_xor_sync(0xffffffffu, rs0, 1);
            rs0 += __shfl_xor_sync(0xffffffffu, rs0, 2);
            rs1 += __shfl_xor_sync(0xffffffffu, rs1, 1);
            rs1 += __shfl_xor_sync(0xffffffffu, rs1, 2);
            lrow[mt][0] = lrow[mt][0] * al0 + rs0;
            lrow[mt][1] = lrow[mt][1] * al1 + rs1;

#pragma unroll
            for (int dt = 0; dt < 8; dt++) {
                o[mt][dt][0] *= al0; o[mt][dt][1] *= al0;
                o[mt][dt][2] *= al1; o[mt][dt][3] *= al1;
            }
        }

        // ---- stash P (tf32) into this warp's rows ----
#pragma unroll
        for (int mt = 0; mt < 2; mt++) {
            int r = (wid << 5) + (mt << 4) + g;
#pragma unroll
            for (int nt = 0; nt < 8; nt++) {
                *(float2*)&Ps[r * PST + (nt << 3) + (t << 1)]
                    = make_float2(tff(s[mt][nt][0]), tff(s[mt][nt][1]));
                *(float2*)&Ps[(r + 8) * PST + (nt << 3) + (t << 1)]
                    = make_float2(tff(s[mt][nt][2]), tff(s[mt][nt][3]));
            }
        }
        __syncwarp();

        // ---- O += P @ V ----
#pragma unroll
        for (int kblk = 0; kblk < 8; kblk++) {
            int kc = kblk << 3;
            unsigned aF[2][4];
#pragma unroll
            for (int mt = 0; mt < 2; mt++) {
                int r = (wid << 5) + (mt << 4) + g;
                aF[mt][0] = __float_as_uint(Ps[r * PST + kc + t]);
                aF[mt][1] = __float_as_uint(Ps[(r + 8) * PST + kc + t]);
                aF[mt][2] = __float_as_uint(Ps[r * PST + kc + t + 4]);
                aF[mt][3] = __float_as_uint(Ps[(r + 8) * PST + kc + t + 4]);
            }
#pragma unroll
            for (int dt = 0; dt < 8; dt++) {
                float2 bb = *(const float2*)&Vs[((dt << 3) + kblk) * 64 + (g << 3) + (t << 1)];
                unsigned b0 = __float_as_uint(bb.x), b1 = __float_as_uint(bb.y);
                mma8(o[0][dt], aF[0], b0, b1);
                mma8(o[1][dt], aF[1], b0, b1);
            }
        }
    }

    // ---- normalize + write [b, t, h*64+d] ----
#pragma unroll
    for (int mt = 0; mt < 2; mt++) {
        float inv0 = 1.f / lrow[mt][0], inv1 = 1.f / lrow[mt][1];
        int tq0 = m0 + (wid << 5) + (mt << 4) + g;
#pragma unroll
        for (int dt = 0; dt < 8; dt++) {
            int col = (h << 6) + (dt << 3) + (t << 1);
            *(float2*)&g_ao[(size_t)(b * TT + tq0) * EMB + col]
                = make_float2(o[mt][dt][0] * inv0, o[mt][dt][1] * inv0);
            *(float2*)&g_ao[(size_t)(b * TT + tq0 + 8) * EMB + col]
                = make_float2(o[mt][dt][2] * inv1, o[mt][dt][3] * inv1);
        }
    }
}

// ============================================================================
extern "C" void kernel_launch(void* const* d_in, const int* in_sizes, int n_in,
                              void* d_out, int out_size)
{
    (void)in_sizes; (void)n_in; (void)out_size;
    const float*         query = (const float*)d_in[0];
    const float*         key   = (const float*)d_in[1];
    const float*         value = (const float*)d_in[2];
    const unsigned char* kpm   = (const unsigned char*)d_in[3];
    const float*         amask = (const float*)d_in[4];
    const float*         win   = (const float*)d_in[5];
    const float*         bin   = (const float*)d_in[6];
    const float*         wout  = (const float*)d_in[7];
    const float*         bout  = (const float*)d_in[8];
    float*               out   = (float*)d_out;

    float *pq, *pk, *pv, *pao;
    cudaGetSymbolAddress((void**)&pq,  g_q);
    cudaGetSymbolAddress((void**)&pk,  g_k);
    cudaGetSymbolAddress((void**)&pv,  g_v);
    cudaGetSymbolAddress((void**)&pao, g_ao);

    dim3 gg(EMB / 128, NTOK / 128);   // (8, 64)

    // Q/K/V projections (scatter into [b,h,t,d])
    gemm_tf32<<<gg, 256>>>(query, win,               bin,        pq, 1);
    gemm_tf32<<<gg, 256>>>(key,   win +   1024*1024, bin + 1024, pk, 1);
    gemm_tf32<<<gg, 256>>>(value, win + 2*1024*1024, bin + 2048, pv, 1);

    // Flash attention: BM=128 -> grid.y = TT/128  (R9 bug: was TT/64 -> OOB)
    cudaFuncSetAttribute(flash_tf32,
                         cudaFuncAttributeMaxDynamicSharedMemorySize, FLASH_SMEM);
    flash_tf32<<<dim3(BHD, TT / 128), 128, FLASH_SMEM>>>(amask, kpm);

    // Output projection -> d_out
    gemm_tf32<<<gg, 256>>>(pao, wout, bout, out, 0);
}

// round 11
// speedup vs baseline: 1.3900x; 1.3900x over previous
#include <cuda_runtime.h>
#include <math.h>

// Problem constants
#define BQ    8
#define TT    1024
#define EMB   1024
#define NH    16
#define DH    64
#define NTOK  (BQ*TT)      // 8192
#define BHD   (BQ*NH)      // 128

#define LOG2E 1.4426950408889634f

// -------- scratch (static device arrays: no allocation APIs allowed) --------
__device__ float g_q  [BHD*TT*DH];   // [b,h,t,d]
__device__ float g_k  [BHD*TT*DH];
__device__ float g_v  [BHD*TT*DH];
__device__ float g_ao [NTOK*EMB];    // attention output [b*t, h*d]
__device__ float g_am2[TT*TT];       // amask * LOG2E

// ---------------------------------------------------------------------------
// helpers
// ---------------------------------------------------------------------------
__device__ __forceinline__ unsigned f2tf(float x) {
    unsigned u;
    asm("cvt.rna.tf32.f32 %0, %1;" : "=r"(u) : "f"(x));
    return u;
}
__device__ __forceinline__ float tff(float x) { return __uint_as_float(f2tf(x)); }
__device__ __forceinline__ float4 tff4(float4 v) {
    return make_float4(tff(v.x), tff(v.y), tff(v.z), tff(v.w));
}

__device__ __forceinline__ void mma8(float* d, const unsigned* a, unsigned b0, unsigned b1) {
    asm volatile(
        "mma.sync.aligned.m16n8k8.row.col.f32.tf32.tf32.f32 "
        "{%0,%1,%2,%3}, {%4,%5,%6,%7}, {%8,%9}, {%0,%1,%2,%3};\n"
        : "+f"(d[0]), "+f"(d[1]), "+f"(d[2]), "+f"(d[3])
        : "r"(a[0]), "r"(a[1]), "r"(a[2]), "r"(a[3]), "r"(b0), "r"(b1));
}

// FMA-only exp2 (no MUFU). y <= 0 expected; clamped below -126 -> ~0.
__device__ __forceinline__ float exp2_fast(float y) {
    y = fmaxf(y, -126.0f);
    float r  = y + 12582912.0f;
    int   n  = __float_as_int(r) - 0x4B400000;
    float f  = y - (r - 12582912.0f);
    float p  =            1.3333558146428443e-3f;
    p = fmaf(p, f,        9.6181291076284771e-3f);
    p = fmaf(p, f,        5.5504108664821580e-2f);
    p = fmaf(p, f,        2.4022650695910072e-1f);
    p = fmaf(p, f,        6.9314718055994531e-1f);
    p = fmaf(p, f,        1.0f);
    return p * __int_as_float((n + 127) << 23);
}

// ---------------------------------------------------------------------------
// prep: amask * LOG2E  (run once per launch, ~8us)
// ---------------------------------------------------------------------------
__global__ void prep_mask(const float* __restrict__ am) {
    int i = (blockIdx.x * 256 + threadIdx.x) * 4;
    float4 v = *(const float4*)(am + i);
    v.x *= LOG2E; v.y *= LOG2E; v.z *= LOG2E; v.w *= LOG2E;
    *(float4*)&g_am2[i] = v;
}

// ---------------------------------------------------------------------------
// tf32 GEMM, 2-stage pipelined. C[m][n] = sum_k A[m][k]*B[n][k] + bias[n]
// M=8192 N=1024 K=1024. 128x128 tile, BK=32, 256 thr, warp tile 32x64.
// grid.z selects A/C (QKV merged); mode 0: row-major C ; 1: [b,h,t,d] scatter
// ---------------------------------------------------------------------------
__global__ __launch_bounds__(256, 2)
void gemm_tf32(const float* __restrict__ A0, const float* __restrict__ A1,
               const float* __restrict__ A2, const float* __restrict__ B0,
               const float* __restrict__ bias0,
               float* __restrict__ C0, float* __restrict__ C1, float* __restrict__ C2,
               int mode)
{
    __shared__ float As[2][128 * 36];
    __shared__ float Bs[2][128 * 36];

    const int z = blockIdx.z;
    const float* A    = (z == 0) ? A0 : (z == 1) ? A1 : A2;
    const float* B    = B0 + (size_t)z * 1024 * 1024;
    const float* bias = bias0 + z * 1024;
    float*       C    = (z == 0) ? C0 : (z == 1) ? C1 : C2;

    const int tid  = threadIdx.x;
    const int lane = tid & 31, wid = tid >> 5;
    const int g = lane >> 2, t = lane & 3;
    const int wm = (wid >> 1) * 32, wn = (wid & 1) * 64;
    const int m0 = blockIdx.y * 128, n0 = blockIdx.x * 128;

    const int krow = tid >> 3;          // 0..31
    const int kf   = (tid & 7) * 4;     // 0..28

    float acc[2][8][4];
#pragma unroll
    for (int mt = 0; mt < 2; mt++)
#pragma unroll
        for (int nt = 0; nt < 8; nt++)
#pragma unroll
            for (int c = 0; c < 4; c++) acc[mt][nt][c] = 0.f;

    // prologue: stage 0
#pragma unroll
    for (int j = 0; j < 4; j++) {
        int row = krow + 32 * j;
        float4 a = *(const float4*)(A + (size_t)(m0 + row) * 1024 + kf);
        float4 b = *(const float4*)(B + (size_t)(n0 + row) * 1024 + kf);
        *(float4*)&As[0][row * 36 + kf] = tff4(a);
        *(float4*)&Bs[0][row * 36 + kf] = tff4(b);
    }
    __syncthreads();

    int st = 0;
    for (int kb = 0; kb < 1024; kb += 32) {
        const bool more = (kb + 32) < 1024;
        float4 pa[2], pb[2];

        if (more) {
#pragma unroll
            for (int j = 0; j < 2; j++) {
                int row = krow + 32 * j;
                pa[j] = *(const float4*)(A + (size_t)(m0 + row) * 1024 + kb + 32 + kf);
                pb[j] = *(const float4*)(B + (size_t)(n0 + row) * 1024 + kb + 32 + kf);
            }
        }
        // compute kc = 0, 8
#pragma unroll
        for (int kc = 0; kc < 16; kc += 8) {
            unsigned aF[2][4];
#pragma unroll
            for (int mt = 0; mt < 2; mt++) {
                int r = wm + mt * 16 + g;
                aF[mt][0] = __float_as_uint(As[st][r * 36 + kc + t]);
                aF[mt][1] = __float_as_uint(As[st][(r + 8) * 36 + kc + t]);
                aF[mt][2] = __float_as_uint(As[st][r * 36 + kc + t + 4]);
                aF[mt][3] = __float_as_uint(As[st][(r + 8) * 36 + kc + t + 4]);
            }
#pragma unroll
            for (int nt = 0; nt < 8; nt++) {
                int c = wn + nt * 8 + g;
                unsigned b0 = __float_as_uint(Bs[st][c * 36 + kc + t]);
                unsigned b1 = __float_as_uint(Bs[st][c * 36 + kc + t + 4]);
                mma8(acc[0][nt], aF[0], b0, b1);
                mma8(acc[1][nt], aF[1], b0, b1);
            }
        }
        if (more) {
#pragma unroll
            for (int j = 0; j < 2; j++) {
                int row = krow + 32 * j;
                *(float4*)&As[st ^ 1][row * 36 + kf] = tff4(pa[j]);
                *(float4*)&Bs[st ^ 1][row * 36 + kf] = tff4(pb[j]);
            }
#pragma unroll
            for (int j = 0; j < 2; j++) {
                int row = krow + 32 * (j + 2);
                pa[j] = *(const float4*)(A + (size_t)(m0 + row) * 1024 + kb + 32 + kf);
                pb[j] = *(const float4*)(B + (size_t)(n0 + row) * 1024 + kb + 32 + kf);
            }
        }
        // compute kc = 16, 24
#pragma unroll
        for (int kc = 16; kc < 32; kc += 8) {
            unsigned aF[2][4];
#pragma unroll
            for (int mt = 0; mt < 2; mt++) {
                int r = wm + mt * 16 + g;
                aF[mt][0] = __float_as_uint(As[st][r * 36 + kc + t]);
                aF[mt][1] = __float_as_uint(As[st][(r + 8) * 36 + kc + t]);
                aF[mt][2] = __float_as_uint(As[st][r * 36 + kc + t + 4]);
                aF[mt][3] = __float_as_uint(As[st][(r + 8) * 36 + kc + t + 4]);
            }
#pragma unroll
            for (int nt = 0; nt < 8; nt++) {
                int c = wn + nt * 8 + g;
                unsigned b0 = __float_as_uint(Bs[st][c * 36 + kc + t]);
                unsigned b1 = __float_as_uint(Bs[st][c * 36 + kc + t + 4]);
                mma8(acc[0][nt], aF[0], b0, b1);
                mma8(acc[1][nt], aF[1], b0, b1);
            }
        }
        if (more) {
#pragma unroll
            for (int j = 0; j < 2; j++) {
                int row = krow + 32 * (j + 2);
                *(float4*)&As[st ^ 1][row * 36 + kf] = tff4(pa[j]);
                *(float4*)&Bs[st ^ 1][row * 36 + kf] = tff4(pb[j]);
            }
            st ^= 1;
        }
        __syncthreads();
    }

#pragma unroll
    for (int nt = 0; nt < 8; nt++) {
        int n = n0 + wn + nt * 8 + 2 * t;
        float bv0 = bias[n], bv1 = bias[n + 1];
#pragma unroll
        for (int mt = 0; mt < 2; mt++) {
            int r = m0 + wm + mt * 16 + g;
            float2 v0 = make_float2(acc[mt][nt][0] + bv0, acc[mt][nt][1] + bv1);
            float2 v1 = make_float2(acc[mt][nt][2] + bv0, acc[mt][nt][3] + bv1);
            if (mode == 0) {
                *(float2*)&C[(size_t)r * 1024 + n]       = v0;
                *(float2*)&C[(size_t)(r + 8) * 1024 + n] = v1;
            } else {
                int h = n >> 6, d = n & 63;
                int bb = r >> 10, tq = r & 1023;
                *(float2*)&C[(size_t)((bb * NH + h) * TT + tq) * DH + d]     = v0;
                *(float2*)&C[(size_t)((bb * NH + h) * TT + tq + 8) * DH + d] = v1;
            }
        }
    }
}

// ---------------------------------------------------------------------------
// Flash attention, tf32 MMA. BM=128, BN=64, Dh=64. 256 thr / 8 warps;
// warp w owns rows [16w,16w+16) exclusively -> quad-local softmax.
// amask pre-scaled by LOG2E (g_am2); kpm via warp-uniform fast path.
// ---------------------------------------------------------------------------
#define FQ 68   // stride for Qs/Ks/Ps
#define FV 72   // stride for Vs
#define FLASH_SMEM ((128*FQ + 64*FQ + 64*FV + 128*FQ) * 4)   // 105472 B

__global__ __launch_bounds__(256, 2)
void flash_tf32(const unsigned char* __restrict__ kpm)
{
    extern __shared__ float sm[];
    float* Qs = sm;                    // [128][FQ]
    float* Ks = Qs + 128 * FQ;         // [64][FQ]
    float* Vs = Ks + 64 * FQ;          // [64][FV]
    float* Ps = Vs + 64 * FV;          // [128][FQ]

    const int tid  = threadIdx.x;
    const int lane = tid & 31, wid = tid >> 5;
    const int g = lane >> 2, t = lane & 3;
    const int bh = blockIdx.x, b = bh >> 4, h = bh & 15;
    const int m0 = blockIdx.y * 128;

    const float* Qg = g_q + ((size_t)bh * TT + m0) * DH;
    const float* Kg = g_k + (size_t)bh * TT * DH;
    const float* Vg = g_v + (size_t)bh * TT * DH;

    // load Q tile (tf32-rounded)
#pragma unroll
    for (int j = 0; j < 8; j++) {
        int l = tid + 256 * j;
        int row = l >> 4, fc = (l & 15) * 4;
        float4 q = *(const float4*)(Qg + row * 64 + fc);
        *(float4*)&Qs[row * FQ + fc] = tff4(q);
    }

    float o[8][4];
#pragma unroll
    for (int dt = 0; dt < 8; dt++)
#pragma unroll
        for (int c = 0; c < 4; c++) o[dt][c] = 0.f;

    float mr0 = -1e30f, mr1 = -1e30f, l0 = 0.f, l1 = 0.f;
    const int   r0  = wid * 16 + g;
    const int   tq0 = m0 + r0;
    const float SC2 = 0.125f * LOG2E;

    for (int n0k = 0; n0k < TT; n0k += 64) {
        __syncthreads();   // prior iter done with Ks/Vs
#pragma unroll
        for (int j = 0; j < 4; j++) {
            int l = tid + 256 * j;
            int row = l >> 4, fc = (l & 15) * 4;
            float4 kq = *(const float4*)(Kg + (size_t)(n0k + row) * 64 + fc);
            float4 vq = *(const float4*)(Vg + (size_t)(n0k + row) * 64 + fc);
            *(float4*)&Ks[row * FQ + fc] = tff4(kq);
            *(float4*)&Vs[row * FV + fc] = tff4(vq);
        }
        __syncthreads();

        // warp-uniform padding-mask check for this 64-key tile
        unsigned long long kw = 0;
        if (lane < 8)
            kw = *(const unsigned long long*)(kpm + (b << 10) + n0k + (lane << 3));
        const bool anymask = __any_sync(0xffffffffu, kw != 0ull);

        // ---- S = Q @ K^T ----
        float s[8][4];
#pragma unroll
        for (int nt = 0; nt < 8; nt++)
#pragma unroll
            for (int c = 0; c < 4; c++) s[nt][c] = 0.f;

#pragma unroll
        for (int kc = 0; kc < 64; kc += 8) {
            unsigned aF[4];
            aF[0] = __float_as_uint(Qs[(r0    ) * FQ + kc + t]);
            aF[1] = __float_as_uint(Qs[(r0 + 8) * FQ + kc + t]);
            aF[2] = __float_as_uint(Qs[(r0    ) * FQ + kc + t + 4]);
            aF[3] = __float_as_uint(Qs[(r0 + 8) * FQ + kc + t + 4]);
#pragma unroll
            for (int nt = 0; nt < 8; nt++) {
                unsigned b0 = __float_as_uint(Ks[(nt * 8 + g) * FQ + kc + t]);
                unsigned b1 = __float_as_uint(Ks[(nt * 8 + g) * FQ + kc + t + 4]);
                mma8(s[nt], aF, b0, b1);
            }
        }

        // ---- scale + attn-mask (pre-scaled, base-2 domain) ----
#pragma unroll
        for (int nt = 0; nt < 8; nt++) {
            int col = n0k + nt * 8 + 2 * t;
            float2 ma0 = *(const float2*)(g_am2 + (size_t)tq0 * TT + col);
            float2 ma1 = *(const float2*)(g_am2 + (size_t)(tq0 + 8) * TT + col);
            s[nt][0] = fmaf(s[nt][0], SC2, ma0.x);
            s[nt][1] = fmaf(s[nt][1], SC2, ma0.y);
            s[nt][2] = fmaf(s[nt][2], SC2, ma1.x);
            s[nt][3] = fmaf(s[nt][3], SC2, ma1.y);
        }

        // ---- online softmax ----
        float mx0 = -1e30f, mx1 = -1e30f;
#pragma unroll
        for (int nt = 0; nt < 8; nt++) {
            mx0 = fmaxf(mx0, fmaxf(s[nt][0], s[nt][1]));
            mx1 = fmaxf(mx1, fmaxf(s[nt][2], s[nt][3]));
        }
        mx0 = fmaxf(mx0, __shfl_xor_sync(0xffffffffu, mx0, 1));
        mx0 = fmaxf(mx0, __shfl_xor_sync(0xffffffffu, mx0, 2));
        mx1 = fmaxf(mx1, __shfl_xor_sync(0xffffffffu, mx1, 1));
        mx1 = fmaxf(mx1, __shfl_xor_sync(0xffffffffu, mx1, 2));

        float mn0 = fmaxf(mr0, mx0), mn1 = fmaxf(mr1, mx1);
        float al0 = exp2_fast(mr0 - mn0), al1 = exp2_fast(mr1 - mn1);
        mr0 = mn0; mr1 = mn1;

        float rs0 = 0.f, rs1 = 0.f;
        if (!anymask) {
#pragma unroll
            for (int nt = 0; nt < 8; nt++) {
                s[nt][0] = exp2_fast(s[nt][0] - mn0);
                s[nt][1] = exp2_fast(s[nt][1] - mn0);
                s[nt][2] = exp2_fast(s[nt][2] - mn1);
                s[nt][3] = exp2_fast(s[nt][3] - mn1);
                rs0 += s[nt][0] + s[nt][1];
                rs1 += s[nt][2] + s[nt][3];
            }
        } else {
#pragma unroll
            for (int nt = 0; nt < 8; nt++) {
                s[nt][0] = exp2_fast(s[nt][0] - mn0);
                s[nt][1] = exp2_fast(s[nt][1] - mn0);
                s[nt][2] = exp2_fast(s[nt][2] - mn1);
                s[nt][3] = exp2_fast(s[nt][3] - mn1);
                const unsigned char* kp = kpm + (b << 10) + n0k + (nt << 3) + (t << 1);
                if (kp[0]) { s[nt][0] = 0.f; s[nt][2] = 0.f; }
                if (kp[1]) { s[nt][1] = 0.f; s[nt][3] = 0.f; }
                rs0 += s[nt][0] + s[nt][1];
                rs1 += s[nt][2] + s[nt][3];
            }
        }
        rs0 += __shfl_xor_sync(0xffffffffu, rs0, 1);
        rs0 += __shfl_xor_sync(0xffffffffu, rs0, 2);
        rs1 += __shfl_xor_sync(0xffffffffu, rs1, 1);
        rs1 += __shfl_xor_sync(0xffffffffu, rs1, 2);
        l0 = l0 * al0 + rs0;
        l1 = l1 * al1 + rs1;

        // skip o-rescale when no new max anywhere in the warp (common later iters)
        if (!__all_sync(0xffffffffu, (al0 == 1.0f) & (al1 == 1.0f))) {
#pragma unroll
            for (int dt = 0; dt < 8; dt++) {
                o[dt][0] *= al0; o[dt][1] *= al0;
                o[dt][2] *= al1; o[dt][3] *= al1;
            }
        }

        // ---- stash P (tf32) into per-warp smem rows ----
#pragma unroll
        for (int nt = 0; nt < 8; nt++) {
            float2 p0 = make_float2(tff(s[nt][0]), tff(s[nt][1]));
            float2 p1 = make_float2(tff(s[nt][2]), tff(s[nt][3]));
            *(float2*)&Ps[(r0    ) * FQ + nt * 8 + 2 * t] = p0;
            *(float2*)&Ps[(r0 + 8) * FQ + nt * 8 + 2 * t] = p1;
        }
        __syncwarp();

        // ---- O += P @ V ----
#pragma unroll
        for (int kc = 0; kc < 64; kc += 8) {
            unsigned aF[4];
            aF[0] = __float_as_uint(Ps[(r0    ) * FQ + kc + t]);
            aF[1] = __float_as_uint(Ps[(r0 + 8) * FQ + kc + t]);
            aF[2] = __float_as_uint(Ps[(r0    ) * FQ + kc + t + 4]);
            aF[3] = __float_as_uint(Ps[(r0 + 8) * FQ + kc + t + 4]);
#pragma unroll
            for (int dt = 0; dt < 8; dt++) {
                unsigned b0 = __float_as_uint(Vs[(kc + t    ) * FV + dt * 8 + g]);
                unsigned b1 = __float_as_uint(Vs[(kc + t + 4) * FV + dt * 8 + g]);
                mma8(o[dt], aF, b0, b1);
            }
        }
    }

    // ---- normalize + write [b, t, h*64+d] ----
    float inv0 = 1.f / l0, inv1 = 1.f / l1;
#pragma unroll
    for (int dt = 0; dt < 8; dt++) {
        int col = h * 64 + dt * 8 + 2 * t;
        float2 v0 = make_float2(o[dt][0] * inv0, o[dt][1] * inv0);
        float2 v1 = make_float2(o[dt][2] * inv1, o[dt][3] * inv1);
        *(float2*)&g_ao[(size_t)(b * TT + tq0    ) * EMB + col] = v0;
        *(float2*)&g_ao[(size_t)(b * TT + tq0 + 8) * EMB + col] = v1;
    }
}

// ============================================================================
extern "C" void kernel_launch(void* const* d_in, const int* in_sizes, int n_in,
                              void* d_out, int out_size)
{
    (void)in_sizes; (void)n_in; (void)out_size;
    const float*         query = (const float*)d_in[0];
    const float*         key   = (const float*)d_in[1];
    const float*         value = (const float*)d_in[2];
    const unsigned char* kpm   = (const unsigned char*)d_in[3];
    const float*         amask = (const float*)d_in[4];
    const float*         win   = (const float*)d_in[5];
    const float*         bin   = (const float*)d_in[6];
    const float*         wout  = (const float*)d_in[7];
    const float*         bout  = (const float*)d_in[8];
    float*               out   = (float*)d_out;

    float *pq, *pk, *pv, *pao;
    cudaGetSymbolAddress((void**)&pq,  g_q);
    cudaGetSymbolAddress((void**)&pk,  g_k);
    cudaGetSymbolAddress((void**)&pv,  g_v);
    cudaGetSymbolAddress((void**)&pao, g_ao);

    // amask * LOG2E (overlaps nothing, but tiny)
    prep_mask<<<1024, 256>>>(amask);

    // Q/K/V projections merged into one launch (grid.z = 3)
    gemm_tf32<<<dim3(8, 64, 3), 256>>>(query, key, value, win, bin,
                                       pq, pk, pv, 1);

    // Flash attention: BM=128, 256 threads
    cudaFuncSetAttribute(flash_tf32,
                         cudaFuncAttributeMaxDynamicSharedMemorySize, FLASH_SMEM);
    flash_tf32<<<dim3(BHD, TT / 128), 256, FLASH_SMEM>>>(kpm);

    // Output projection -> d_out
    gemm_tf32<<<dim3(8, 64, 1), 256>>>(pao, pao, pao, wout, bout,
                                       out, out, out, 0);
}

// round 12
// speedup vs baseline: 1.3948x; 1.0034x over previous
#include <cuda_runtime.h>
#include <cuda_fp16.h>
#include <math.h>

// Problem constants
#define BQ    8
#define TT    1024
#define EMB   1024
#define NH    16
#define DH    64
#define NTOK  (BQ*TT)      // 8192
#define BHD   (BQ*NH)      // 128

#define LOG2E 1.4426950408889634f

// -------- scratch (static device arrays: no allocation APIs allowed) --------
__device__ float g_q  [BHD*TT*DH];   // [b,h,t,d]
__device__ float g_k  [BHD*TT*DH];
__device__ float g_v  [BHD*TT*DH];
__device__ float g_ao [NTOK*EMB];    // attention output [b*t, h*d]
__device__ float g_am2[TT*TT];       // amask * LOG2E

// ---------------------------------------------------------------------------
// helpers
// ---------------------------------------------------------------------------
__device__ __forceinline__ void mma16(float* d, const unsigned* a, unsigned b0, unsigned b1) {
    asm volatile(
        "mma.sync.aligned.m16n8k16.row.col.f32.f16.f16.f32 "
        "{%0,%1,%2,%3}, {%4,%5,%6,%7}, {%8,%9}, {%0,%1,%2,%3};\n"
        : "+f"(d[0]), "+f"(d[1]), "+f"(d[2]), "+f"(d[3])
        : "r"(a[0]), "r"(a[1]), "r"(a[2]), "r"(a[3]), "r"(b0), "r"(b1));
}

__device__ __forceinline__ unsigned h2u(__half2 h) { return *(unsigned*)&h; }
__device__ __forceinline__ __half2 pack2(float x, float y) { return __floats2half2_rn(x, y); }

// FMA-only exp2 (no MUFU). y <= 0 expected; clamped below -126 -> ~0.
__device__ __forceinline__ float exp2_fast(float y) {
    y = fmaxf(y, -126.0f);
    float r  = y + 12582912.0f;
    int   n  = __float_as_int(r) - 0x4B400000;
    float f  = y - (r - 12582912.0f);
    float p  =            1.3333558146428443e-3f;
    p = fmaf(p, f,        9.6181291076284771e-3f);
    p = fmaf(p, f,        5.5504108664821580e-2f);
    p = fmaf(p, f,        2.4022650695910072e-1f);
    p = fmaf(p, f,        6.9314718055994531e-1f);
    p = fmaf(p, f,        1.0f);
    return p * __int_as_float((n + 127) << 23);
}

// ---------------------------------------------------------------------------
// prep: amask * LOG2E  (run once per launch, ~8us)
// ---------------------------------------------------------------------------
__global__ void prep_mask(const float* __restrict__ am) {
    int i = (blockIdx.x * 256 + threadIdx.x) * 4;
    float4 v = *(const float4*)(am + i);
    v.x *= LOG2E; v.y *= LOG2E; v.z *= LOG2E; v.w *= LOG2E;
    *(float4*)&g_am2[i] = v;
}

// ---------------------------------------------------------------------------
// fp16 GEMM (fp32 accum), 2-stage pipelined. C = A*B^T + bias.
// M=8192 N=1024 K=1024. 128x128 tile, BK=32, 256 thr, warp tile 32x64,
// mma m16n8k16. Smem rows: 16 half2 data + pad -> stride 20 half2
// (banks 20g+t distinct mod 32 => conflict-free fragment loads).
// grid.z selects A/C (QKV merged). mode 0: row-major C ; 1: [b,h,t,d] scatter
// ---------------------------------------------------------------------------
__global__ __launch_bounds__(256, 2)
void gemm_fp16(const float* __restrict__ A0, const float* __restrict__ A1,
               const float* __restrict__ A2, const float* __restrict__ B0,
               const float* __restrict__ bias0,
               float* __restrict__ C0, float* __restrict__ C1, float* __restrict__ C2,
               int mode)
{
    __shared__ __half2 As[2][128 * 20];
    __shared__ __half2 Bs[2][128 * 20];

    const int z = blockIdx.z;
    const float* A    = (z == 0) ? A0 : (z == 1) ? A1 : A2;
    const float* B    = B0 + (size_t)z * 1024 * 1024;
    const float* bias = bias0 + z * 1024;
    float*       C    = (z == 0) ? C0 : (z == 1) ? C1 : C2;

    const int tid  = threadIdx.x;
    const int lane = tid & 31, wid = tid >> 5;
    const int g = lane >> 2, t = lane & 3;
    const int wm = (wid >> 1) * 32, wn = (wid & 1) * 64;
    const int m0 = blockIdx.y * 128, n0 = blockIdx.x * 128;

    // loader: 2 threads per row, each covers 16 floats (4 float4)
    const int lrow  = tid >> 1;                  // 0..127
    const int hkf   = (tid & 1) << 4;            // float offset 0 / 16
    const int sbase = lrow * 20 + ((tid & 1) << 3);  // half2 offset

    float acc[2][8][4];
#pragma unroll
    for (int mt = 0; mt < 2; mt++)
#pragma unroll
        for (int nt = 0; nt < 8; nt++)
#pragma unroll
            for (int c = 0; c < 4; c++) acc[mt][nt][c] = 0.f;

    const float* pArow = A + (size_t)(m0 + lrow) * 1024 + hkf;
    const float* pBrow = B + (size_t)(n0 + lrow) * 1024 + hkf;

    // prologue: stage 0
#pragma unroll
    for (int j = 0; j < 4; j++) {
        float4 a = *(const float4*)(pArow + 4 * j);
        float4 b = *(const float4*)(pBrow + 4 * j);
        As[0][sbase + 2*j]     = pack2(a.x, a.y);
        As[0][sbase + 2*j + 1] = pack2(a.z, a.w);
        Bs[0][sbase + 2*j]     = pack2(b.x, b.y);
        Bs[0][sbase + 2*j + 1] = pack2(b.z, b.w);
    }
    __syncthreads();

    int st = 0;
    for (int kb = 0; kb < 1024; kb += 32) {
        const bool more = (kb + 32) < 1024;
        float4 pa[2], pb[2];
        if (more) {
#pragma unroll
            for (int j = 0; j < 2; j++) {
                pa[j] = *(const float4*)(pArow + kb + 32 + 4 * j);
                pb[j] = *(const float4*)(pBrow + kb + 32 + 4 * j);
            }
        }
        // compute kc16 = 0  (k halves 0..15 -> half2 offset 0..7)
        {
            unsigned aF[2][4];
#pragma unroll
            for (int mt = 0; mt < 2; mt++) {
                int r = wm + mt * 16 + g;
                aF[mt][0] = h2u(As[st][r * 20 + t]);
                aF[mt][1] = h2u(As[st][(r + 8) * 20 + t]);
                aF[mt][2] = h2u(As[st][r * 20 + t + 4]);
                aF[mt][3] = h2u(As[st][(r + 8) * 20 + t + 4]);
            }
#pragma unroll
            for (int nt = 0; nt < 8; nt++) {
                int c = wn + nt * 8 + g;
                unsigned b0 = h2u(Bs[st][c * 20 + t]);
                unsigned b1 = h2u(Bs[st][c * 20 + t + 4]);
                mma16(acc[0][nt], aF[0], b0, b1);
                mma16(acc[1][nt], aF[1], b0, b1);
            }
        }
        if (more) {
#pragma unroll
            for (int j = 0; j < 2; j++) {
                As[st ^ 1][sbase + 2*j]     = pack2(pa[j].x, pa[j].y);
                As[st ^ 1][sbase + 2*j + 1] = pack2(pa[j].z, pa[j].w);
                Bs[st ^ 1][sbase + 2*j]     = pack2(pb[j].x, pb[j].y);
                Bs[st ^ 1][sbase + 2*j + 1] = pack2(pb[j].z, pb[j].w);
            }
#pragma unroll
            for (int j = 0; j < 2; j++) {
                pa[j] = *(const float4*)(pArow + kb + 32 + 8 + 4 * j);
                pb[j] = *(const float4*)(pBrow + kb + 32 + 8 + 4 * j);
            }
        }
        // compute kc16 = 1  (k halves 16..31 -> half2 offset 8..15)
        {
            unsigned aF[2][4];
#pragma unroll
            for (int mt = 0; mt < 2; mt++) {
                int r = wm + mt * 16 + g;
                aF[mt][0] = h2u(As[st][r * 20 + 8 + t]);
                aF[mt][1] = h2u(As[st][(r + 8) * 20 + 8 + t]);
                aF[mt][2] = h2u(As[st][r * 20 + 8 + t + 4]);
                aF[mt][3] = h2u(As[st][(r + 8) * 20 + 8 + t + 4]);
            }
#pragma unroll
            for (int nt = 0; nt < 8; nt++) {
                int c = wn + nt * 8 + g;
                unsigned b0 = h2u(Bs[st][c * 20 + 8 + t]);
                unsigned b1 = h2u(Bs[st][c * 20 + 8 + t + 4]);
                mma16(acc[0][nt], aF[0], b0, b1);
                mma16(acc[1][nt], aF[1], b0, b1);
            }
        }
        if (more) {
#pragma unroll
            for (int j = 0; j < 2; j++) {
                As[st ^ 1][sbase + 4 + 2*j]     = pack2(pa[j].x, pa[j].y);
                As[st ^ 1][sbase + 4 + 2*j + 1] = pack2(pa[j].z, pa[j].w);
                Bs[st ^ 1][sbase + 4 + 2*j]     = pack2(pb[j].x, pb[j].y);
                Bs[st ^ 1][sbase + 4 + 2*j + 1] = pack2(pb[j].z, pb[j].w);
            }
            st ^= 1;
        }
        __syncthreads();
    }

#pragma unroll
    for (int nt = 0; nt < 8; nt++) {
        int n = n0 + wn + nt * 8 + 2 * t;
        float bv0 = bias[n], bv1 = bias[n + 1];
#pragma unroll
        for (int mt = 0; mt < 2; mt++) {
            int r = m0 + wm + mt * 16 + g;
            float2 v0 = make_float2(acc[mt][nt][0] + bv0, acc[mt][nt][1] + bv1);
            float2 v1 = make_float2(acc[mt][nt][2] + bv0, acc[mt][nt][3] + bv1);
            if (mode == 0) {
                *(float2*)&C[(size_t)r * 1024 + n]       = v0;
                *(float2*)&C[(size_t)(r + 8) * 1024 + n] = v1;
            } else {
                int h = n >> 6, d = n & 63;
                int bb = r >> 10, tq = r & 1023;
                *(float2*)&C[(size_t)((bb * NH + h) * TT + tq) * DH + d]     = v0;
                *(float2*)&C[(size_t)((bb * NH + h) * TT + tq + 8) * DH + d] = v1;
            }
        }
    }
}

// ---------------------------------------------------------------------------
// Flash attention, fp16 MMA (fp32 accum). BM=128, BN=64, Dh=64.
// 256 thr / 8 warps; warp w owns rows [16w,16w+16) -> quad-local softmax.
// Smem half2, row stride 36 (banks 4g+t = lane). V stored transposed
// [d][tokpair] with XOR swizzle tp^(d>>3): conflict-free fill + frag loads.
// ---------------------------------------------------------------------------
#define FST 36   // half2 stride
#define FLASH_SMEM ((128*FST + 64*FST + 64*FST + 128*FST) * 4)   // 55296 B

__global__ __launch_bounds__(256, 2)
void flash_fp16(const unsigned char* __restrict__ kpm)
{
    extern __shared__ __half2 smh[];
    __half2* Qs = smh;                  // [128][36]
    __half2* Ks = Qs + 128 * FST;       // [64][36]   (row=token, k=d)
    __half2* Vs = Ks + 64 * FST;        // [64][36]   (row=d, cols=tokpair, swizzled)
    __half2* Ps = Vs + 64 * FST;        // [128][36]

    const int tid  = threadIdx.x;
    const int lane = tid & 31, wid = tid >> 5;
    const int g = lane >> 2, t = lane & 3;
    const int bh = blockIdx.x, b = bh >> 4, h = bh & 15;
    const int m0 = blockIdx.y * 128;

    const float* Qg = g_q + ((size_t)bh * TT + m0) * DH;
    const float* Kg = g_k + (size_t)bh * TT * DH;
    const float* Vg = g_v + (size_t)bh * TT * DH;

    // ---- load Q tile (fp16) ----
#pragma unroll
    for (int j = 0; j < 8; j++) {
        int l = tid + 256 * j;
        int row = l >> 4, fc = (l & 15) * 4;
        float4 q = *(const float4*)(Qg + row * 64 + fc);
        Qs[row * FST + (fc >> 1)]     = pack2(q.x, q.y);
        Qs[row * FST + (fc >> 1) + 1] = pack2(q.z, q.w);
    }

    float o[8][4];
#pragma unroll
    for (int dt = 0; dt < 8; dt++)
#pragma unroll
        for (int c = 0; c < 4; c++) o[dt][c] = 0.f;

    float mr0 = -1e30f, mr1 = -1e30f, l0 = 0.f, l1 = 0.f;
    const int   r0  = wid * 16 + g;
    const int   tq0 = m0 + r0;
    const float SC2 = 0.125f * LOG2E;

    for (int n0k = 0; n0k < TT; n0k += 64) {
        __syncthreads();   // prior iter done with Ks/Vs

        // K tile: [token][d] half2
#pragma unroll
        for (int j = 0; j < 4; j++) {
            int l = tid + 256 * j;
            int row = l >> 4, fc = (l & 15) * 4;
            float4 kq = *(const float4*)(Kg + (size_t)(n0k + row) * 64 + fc);
            Ks[row * FST + (fc >> 1)]     = pack2(kq.x, kq.y);
            Ks[row * FST + (fc >> 1) + 1] = pack2(kq.z, kq.w);
        }
        // V tile transposed: Vs[d][tp ^ (d>>3)] = (V[2tp][d], V[2tp+1][d])
#pragma unroll
        for (int j = 0; j < 8; j++) {
            int l = tid + 256 * j;
            int d  = l & 63;
            int tp = l >> 6;            // 0..31
            float v0 = Vg[(size_t)(n0k + 2 * tp) * 64 + d];
            float v1 = Vg[(size_t)(n0k + 2 * tp + 1) * 64 + d];
            Vs[d * FST + (tp ^ (d >> 3))] = pack2(v0, v1);
        }
        __syncthreads();

        // warp-uniform padding-mask check for this 64-key tile
        unsigned long long kw = 0;
        if (lane < 8)
            kw = *(const unsigned long long*)(kpm + (b << 10) + n0k + (lane << 3));
        const bool anymask = __any_sync(0xffffffffu, kw != 0ull);

        // ---- S = Q @ K^T ----
        float s[8][4];
#pragma unroll
        for (int nt = 0; nt < 8; nt++)
#pragma unroll
            for (int c = 0; c < 4; c++) s[nt][c] = 0.f;

#pragma unroll
        for (int kc = 0; kc < 4; kc++) {           // k16 steps over Dh=64
            unsigned aF[4];
            aF[0] = h2u(Qs[(r0    ) * FST + 8 * kc + t]);
            aF[1] = h2u(Qs[(r0 + 8) * FST + 8 * kc + t]);
            aF[2] = h2u(Qs[(r0    ) * FST + 8 * kc + t + 4]);
            aF[3] = h2u(Qs[(r0 + 8) * FST + 8 * kc + t + 4]);
#pragma unroll
            for (int nt = 0; nt < 8; nt++) {
                unsigned b0 = h2u(Ks[(nt * 8 + g) * FST + 8 * kc + t]);
                unsigned b1 = h2u(Ks[(nt * 8 + g) * FST + 8 * kc + t + 4]);
                mma16(s[nt], aF, b0, b1);
            }
        }

        // ---- scale + attn-mask (pre-scaled, base-2 domain) ----
#pragma unroll
        for (int nt = 0; nt < 8; nt++) {
            int col = n0k + nt * 8 + 2 * t;
            float2 ma0 = *(const float2*)(g_am2 + (size_t)tq0 * TT + col);
            float2 ma1 = *(const float2*)(g_am2 + (size_t)(tq0 + 8) * TT + col);
            s[nt][0] = fmaf(s[nt][0], SC2, ma0.x);
            s[nt][1] = fmaf(s[nt][1], SC2, ma0.y);
            s[nt][2] = fmaf(s[nt][2], SC2, ma1.x);
            s[nt][3] = fmaf(s[nt][3], SC2, ma1.y);
        }

        // ---- online softmax ----
        float mx0 = -1e30f, mx1 = -1e30f;
#pragma unroll
        for (int nt = 0; nt < 8; nt++) {
            mx0 = fmaxf(mx0, fmaxf(s[nt][0], s[nt][1]));
            mx1 = fmaxf(mx1, fmaxf(s[nt][2], s[nt][3]));
        }
        mx0 = fmaxf(mx0, __shfl_xor_sync(0xffffffffu, mx0, 1));
        mx0 = fmaxf(mx0, __shfl_xor_sync(0xffffffffu, mx0, 2));
        mx1 = fmaxf(mx1, __shfl_xor_sync(0xffffffffu, mx1, 1));
        mx1 = fmaxf(mx1, __shfl_xor_sync(0xffffffffu, mx1, 2));

        float mn0 = fmaxf(mr0, mx0), mn1 = fmaxf(mr1, mx1);
        float al0 = exp2_fast(mr0 - mn0), al1 = exp2_fast(mr1 - mn1);
        mr0 = mn0; mr1 = mn1;

        float rs0 = 0.f, rs1 = 0.f;
        if (!anymask) {
#pragma unroll
            for (int nt = 0; nt < 8; nt++) {
                s[nt][0] = exp2_fast(s[nt][0] - mn0);
                s[nt][1] = exp2_fast(s[nt][1] - mn0);
                s[nt][2] = exp2_fast(s[nt][2] - mn1);
                s[nt][3] = exp2_fast(s[nt][3] - mn1);
                rs0 += s[nt][0] + s[nt][1];
                rs1 += s[nt][2] + s[nt][3];
            }
        } else {
#pragma unroll
            for (int nt = 0; nt < 8; nt++) {
                s[nt][0] = exp2_fast(s[nt][0] - mn0);
                s[nt][1] = exp2_fast(s[nt][1] - mn0);
                s[nt][2] = exp2_fast(s[nt][2] - mn1);
                s[nt][3] = exp2_fast(s[nt][3] - mn1);
                const unsigned char* kp = kpm + (b << 10) + n0k + (nt << 3) + (t << 1);
                if (kp[0]) { s[nt][0] = 0.f; s[nt][2] = 0.f; }
                if (kp[1]) { s[nt][1] = 0.f; s[nt][3] = 0.f; }
                rs0 += s[nt][0] + s[nt][1];
                rs1 += s[nt][2] + s[nt][3];
            }
        }
        rs0 += __shfl_xor_sync(0xffffffffu, rs0, 1);
        rs0 += __shfl_xor_sync(0xffffffffu, rs0, 2);
        rs1 += __shfl_xor_sync(0xffffffffu, rs1, 1);
        rs1 += __shfl_xor_sync(0xffffffffu, rs1, 2);
        l0 = l0 * al0 + rs0;
        l1 = l1 * al1 + rs1;

        if (!__all_sync(0xffffffffu, (al0 == 1.0f) & (al1 == 1.0f))) {
#pragma unroll
            for (int dt = 0; dt < 8; dt++) {
                o[dt][0] *= al0; o[dt][1] *= al0;
                o[dt][2] *= al1; o[dt][3] *= al1;
            }
        }

        // ---- stash P (fp16) into per-warp smem rows ----
#pragma unroll
        for (int nt = 0; nt < 8; nt++) {
            Ps[(r0    ) * FST + 4 * nt + t] = pack2(s[nt][0], s[nt][1]);
            Ps[(r0 + 8) * FST + 4 * nt + t] = pack2(s[nt][2], s[nt][3]);
        }
        __syncwarp();

        // ---- O += P @ V ----
#pragma unroll
        for (int kc = 0; kc < 4; kc++) {           // k16 steps over 64 keys
            unsigned aF[4];
            aF[0] = h2u(Ps[(r0    ) * FST + 8 * kc + t]);
            aF[1] = h2u(Ps[(r0 + 8) * FST + 8 * kc + t]);
            aF[2] = h2u(Ps[(r0    ) * FST + 8 * kc + t + 4]);
            aF[3] = h2u(Ps[(r0 + 8) * FST + 8 * kc + t + 4]);
#pragma unroll
            for (int dt = 0; dt < 8; dt++) {
                int d0 = dt * 8 + g;
                unsigned b0 = h2u(Vs[d0 * FST + ((t + 8 * kc)     ^ dt)]);
                unsigned b1 = h2u(Vs[d0 * FST + ((t + 4 + 8 * kc) ^ dt)]);
                mma16(o[dt], aF, b0, b1);
            }
        }
    }

    // ---- normalize + write [b, t, h*64+d] ----
    float inv0 = 1.f / l0, inv1 = 1.f / l1;
#pragma unroll
    for (int dt = 0; dt < 8; dt++) {
        int col = h * 64 + dt * 8 + 2 * t;
        float2 v0 = make_float2(o[dt][0] * inv0, o[dt][1] * inv0);
        float2 v1 = make_float2(o[dt][2] * inv1, o[dt][3] * inv1);
        *(float2*)&g_ao[(size_t)(b * TT + tq0    ) * EMB + col] = v0;
        *(float2*)&g_ao[(size_t)(b * TT + tq0 + 8) * EMB + col] = v1;
    }
}

// ============================================================================
extern "C" void kernel_launch(void* const* d_in, const int* in_sizes, int n_in,
                              void* d_out, int out_size)
{
    (void)in_sizes; (void)n_in; (void)out_size;
    const float*         query = (const float*)d_in[0];
    const float*         key   = (const float*)d_in[1];
    const float*         value = (const float*)d_in[2];
    const unsigned char* kpm   = (const unsigned char*)d_in[3];
    const float*         amask = (const float*)d_in[4];
    const float*         win   = (const float*)d_in[5];
    const float*         bin   = (const float*)d_in[6];
    const float*         wout  = (const float*)d_in[7];
    const float*         bout  = (const float*)d_in[8];
    float*               out   = (float*)d_out;

    float *pq, *pk, *pv, *pao;
    cudaGetSymbolAddress((void**)&pq,  g_q);
    cudaGetSymbolAddress((void**)&pk,  g_k);
    cudaGetSymbolAddress((void**)&pv,  g_v);
    cudaGetSymbolAddress((void**)&pao, g_ao);

    // amask * LOG2E
    prep_mask<<<1024, 256>>>(amask);

    // Q/K/V projections merged into one launch (grid.z = 3)
    gemm_fp16<<<dim3(8, 64, 3), 256>>>(query, key, value, win, bin,
                                       pq, pk, pv, 1);

    // Flash attention: BM=128, 256 threads
    cudaFuncSetAttribute(flash_fp16,
                         cudaFuncAttributeMaxDynamicSharedMemorySize, FLASH_SMEM);
    flash_fp16<<<dim3(BHD, TT / 128), 256, FLASH_SMEM>>>(kpm);

    // Output projection -> d_out
    gemm_fp16<<<dim3(8, 64, 1), 256>>>(pao, pao, pao, wout, bout,
                                       out, out, out, 0);
}

// round 14
// speedup vs baseline: 2.3559x; 1.6892x over previous
#include <cuda_runtime.h>
#include <cuda_fp16.h>
#include <stdint.h>
#include <math.h>

// Problem constants
#define BQ    8
#define TT    1024
#define EMB   1024
#define NH    16
#define DH    64
#define NTOK  (BQ*TT)      // 8192
#define BHD   (BQ*NH)      // 128

#define LOG2E 1.4426950408889634f

// -------- scratch (static device arrays: no allocation APIs allowed) --------
__device__ __half g_q16 [NTOK*EMB];     // fp16 copies of inputs
__device__ __half g_k16 [NTOK*EMB];
__device__ __half g_v16 [NTOK*EMB];
__device__ __half g_w16 [3*EMB*EMB];    // in_proj_weight fp16
__device__ __half g_wo16[EMB*EMB];      // out_proj_weight fp16
__device__ __half g_qh  [BHD*TT*DH];    // projected Q [b,h,t,d] fp16
__device__ __half g_kh  [BHD*TT*DH];
__device__ __half g_vh  [BHD*TT*DH];
__device__ __half g_ao16[NTOK*EMB];     // attention output [b*t, h*d] fp16
__device__ float  g_am2 [TT*TT];        // amask * LOG2E (fp32)

// ---------------------------------------------------------------------------
// helpers
// ---------------------------------------------------------------------------
__device__ __forceinline__ unsigned h2u(__half2 h) { return *(unsigned*)&h; }
__device__ __forceinline__ __half2 pack2(float x, float y) { return __floats2half2_rn(x, y); }

__device__ __forceinline__ void mma16(float* d, const unsigned* a, unsigned b0, unsigned b1) {
    asm volatile(
        "mma.sync.aligned.m16n8k16.row.col.f32.f16.f16.f32 "
        "{%0,%1,%2,%3}, {%4,%5,%6,%7}, {%8,%9}, {%0,%1,%2,%3};\n"
        : "+f"(d[0]), "+f"(d[1]), "+f"(d[2]), "+f"(d[3])
        : "r"(a[0]), "r"(a[1]), "r"(a[2]), "r"(a[3]), "r"(b0), "r"(b1));
}

__device__ __forceinline__ uint32_t s2u(const void* p) {
    return (uint32_t)__cvta_generic_to_shared(p);
}
__device__ __forceinline__ void ldsm4(unsigned* r, uint32_t addr) {
    asm volatile("ldmatrix.sync.aligned.m8n8.x4.shared.b16 {%0,%1,%2,%3}, [%4];"
                 : "=r"(r[0]), "=r"(r[1]), "=r"(r[2]), "=r"(r[3]) : "r"(addr));
}
__device__ __forceinline__ void ldsm4t(unsigned* r, uint32_t addr) {
    asm volatile("ldmatrix.sync.aligned.m8n8.x4.trans.shared.b16 {%0,%1,%2,%3}, [%4];"
                 : "=r"(r[0]), "=r"(r[1]), "=r"(r[2]), "=r"(r[3]) : "r"(addr));
}
__device__ __forceinline__ void cpa16(uint32_t dst, const void* src) {
    asm volatile("cp.async.ca.shared.global [%0], [%1], 16;" :: "r"(dst), "l"(src));
}
#define CP_COMMIT() asm volatile("cp.async.commit_group;")
#define CP_WAIT(n)  asm volatile("cp.async.wait_group %0;" :: "n"(n))

// FMA-only exp2 (no MUFU). y <= 0 expected; clamped below -126 -> ~0.
__device__ __forceinline__ float exp2_fast(float y) {
    y = fmaxf(y, -126.0f);
    float r  = y + 12582912.0f;
    int   n  = __float_as_int(r) - 0x4B400000;
    float f  = y - (r - 12582912.0f);
    float p  =            1.3333558146428443e-3f;
    p = fmaf(p, f,        9.6181291076284771e-3f);
    p = fmaf(p, f,        5.5504108664821580e-2f);
    p = fmaf(p, f,        2.4022650695910072e-1f);
    p = fmaf(p, f,        6.9314718055994531e-1f);
    p = fmaf(p, f,        1.0f);
    return p * __int_as_float((n + 127) << 23);
}

// ---------------------------------------------------------------------------
// prep kernels
// ---------------------------------------------------------------------------
__global__ void f2h(const float* __restrict__ src, __half* __restrict__ dst) {
    int i = (blockIdx.x * 256 + threadIdx.x) * 8;
    float4 a = *(const float4*)(src + i);
    float4 b = *(const float4*)(src + i + 4);
    __half2 h[4] = { pack2(a.x, a.y), pack2(a.z, a.w), pack2(b.x, b.y), pack2(b.z, b.w) };
    *(uint4*)(dst + i) = *(uint4*)h;
}

__global__ void prep_mask(const float* __restrict__ am) {
    int i = (blockIdx.x * 256 + threadIdx.x) * 4;
    float4 v = *(const float4*)(am + i);
    v.x *= LOG2E; v.y *= LOG2E; v.z *= LOG2E; v.w *= LOG2E;
    *(float4*)&g_am2[i] = v;
}

// ---------------------------------------------------------------------------
// fp16 GEMM (fp32 accum): C = A*B^T + bias. M=8192 N=1024 K=1024.
// 128x128 tile, BK=32, 256 thr, warp tile 32x64, cp.async 2-stage, ldmatrix.
// Smem row = 32 halfs (16 half2) + pad -> stride 20 half2 (80B).
// grid.z selects A/C (QKV merged). mode 0: fp32 row-major to Cf;
// mode 1: fp16 scatter into [b,h,t,d] (H outputs).
// ---------------------------------------------------------------------------
#define GST 20

__global__ __launch_bounds__(256, 2)
void gemm_fp16(const __half* __restrict__ A0, const __half* __restrict__ A1,
               const __half* __restrict__ A2, const __half* __restrict__ Bw,
               const float* __restrict__ bias0,
               __half* __restrict__ H0, __half* __restrict__ H1, __half* __restrict__ H2,
               float* __restrict__ Cf, int mode)
{
    __shared__ __half2 As[2][128 * GST];
    __shared__ __half2 Bs[2][128 * GST];

    const int z = blockIdx.z;
    const __half* A    = (z == 0) ? A0 : (z == 1) ? A1 : A2;
    const __half* B    = Bw + (size_t)z * 1024 * 1024;
    const float*  bias = bias0 + z * 1024;
    __half*       H    = (z == 0) ? H0 : (z == 1) ? H1 : H2;

    const int tid  = threadIdx.x;
    const int lane = tid & 31, wid = tid >> 5;
    const int g = lane >> 2, t = lane & 3;
    const int wm = (wid >> 1) * 32, wn = (wid & 1) * 64;
    const int m0 = blockIdx.y * 128, n0 = blockIdx.x * 128;

    // cp.async loader: warp w covers rows 8w..8w+7 (+64j); conflict-free phases
    const int rpat = (lane >> 3) + (((lane >> 2) & 1) << 2);   // 0,4,1,5,2,6,3,7
    const int chnk = lane & 3;
    const int lr   = (wid << 3) + rpat;

    // ldmatrix lane offsets
    const int arow = (lane & 7) + ((lane >> 3) & 1) * 8, acol = (lane >> 4) * 4;
    const int brow = (lane & 7) + (lane >> 4) * 8,       bcol = ((lane >> 3) & 1) * 4;

    float acc[2][8][4];
#pragma unroll
    for (int mt = 0; mt < 2; mt++)
#pragma unroll
        for (int nt = 0; nt < 8; nt++)
#pragma unroll
            for (int c = 0; c < 4; c++) acc[mt][nt][c] = 0.f;

    // prologue: stage 0
#pragma unroll
    for (int j = 0; j < 2; j++) {
        int r = lr + (j << 6);
        cpa16(s2u(&As[0][r * GST + (chnk << 2)]), A + ((size_t)(m0 + r) << 10) + (chnk << 3));
        cpa16(s2u(&Bs[0][r * GST + (chnk << 2)]), B + ((size_t)(n0 + r) << 10) + (chnk << 3));
    }
    CP_COMMIT();

    int st = 0;
    for (int kb = 0; kb < 1024; kb += 32) {
        if (kb + 32 < 1024) {
#pragma unroll
            for (int j = 0; j < 2; j++) {
                int r = lr + (j << 6);
                cpa16(s2u(&As[st ^ 1][r * GST + (chnk << 2)]),
                      A + ((size_t)(m0 + r) << 10) + kb + 32 + (chnk << 3));
                cpa16(s2u(&Bs[st ^ 1][r * GST + (chnk << 2)]),
                      B + ((size_t)(n0 + r) << 10) + kb + 32 + (chnk << 3));
            }
            CP_COMMIT();
            CP_WAIT(1);
        } else {
            CP_WAIT(0);
        }
        __syncthreads();

#pragma unroll
        for (int kc = 0; kc < 2; kc++) {
            unsigned aF[2][4], bF[4][4];
#pragma unroll
            for (int mt = 0; mt < 2; mt++)
                ldsm4(aF[mt], s2u(&As[st][(wm + 16 * mt + arow) * GST + 8 * kc + acol]));
#pragma unroll
            for (int np = 0; np < 4; np++)
                ldsm4(bF[np], s2u(&Bs[st][(wn + 16 * np + brow) * GST + 8 * kc + bcol]));
#pragma unroll
            for (int mt = 0; mt < 2; mt++)
#pragma unroll
                for (int np = 0; np < 4; np++) {
                    mma16(acc[mt][2 * np],     aF[mt], bF[np][0], bF[np][1]);
                    mma16(acc[mt][2 * np + 1], aF[mt], bF[np][2], bF[np][3]);
                }
        }
        __syncthreads();
        st ^= 1;
    }

#pragma unroll
    for (int nt = 0; nt < 8; nt++) {
        int n = n0 + wn + nt * 8 + 2 * t;
        float bv0 = bias[n], bv1 = bias[n + 1];
#pragma unroll
        for (int mt = 0; mt < 2; mt++) {
            int r = m0 + wm + mt * 16 + g;
            if (mode == 0) {
                *(float2*)&Cf[(size_t)r * 1024 + n]
                    = make_float2(acc[mt][nt][0] + bv0, acc[mt][nt][1] + bv1);
                *(float2*)&Cf[(size_t)(r + 8) * 1024 + n]
                    = make_float2(acc[mt][nt][2] + bv0, acc[mt][nt][3] + bv1);
            } else {
                int h = n >> 6, d = n & 63;
                int bb = r >> 10, tq = r & 1023;
                *(__half2*)&H[(size_t)((bb * NH + h) * TT + tq) * DH + d]
                    = pack2(acc[mt][nt][0] + bv0, acc[mt][nt][1] + bv1);
                *(__half2*)&H[(size_t)((bb * NH + h) * TT + tq + 8) * DH + d]
                    = pack2(acc[mt][nt][2] + bv0, acc[mt][nt][3] + bv1);
            }
        }
    }
}

// ---------------------------------------------------------------------------
// Flash attention, fp16 MMA (fp32 accum). BM=128, BN=64, Dh=64.
// 256 thr / 8 warps; warp w owns rows [16w,16w+16) -> quad-local softmax.
// cp.async 2-stage K/V; ldmatrix frags; P stays in registers (C-frag == A-frag).
// Smem half2 stride 36/row. Layout: Q | K0 V0 | K1 V1.
// ---------------------------------------------------------------------------
#define FST 36
#define QH2  (128 * FST)          // 4608 half2
#define KVH2 (64 * FST)           // 2304 half2
#define FLASH_SMEM ((QH2 + 4 * KVH2) * 4)   // 55296 B

__global__ __launch_bounds__(256, 2)
void flash_fp16(const unsigned char* __restrict__ kpm)
{
    extern __shared__ __half2 smh[];
    __half2* Qs = smh;

    const int tid  = threadIdx.x;
    const int lane = tid & 31, wid = tid >> 5;
    const int g = lane >> 2, t = lane & 3;
    const int bh = blockIdx.x, b = bh >> 4, h = bh & 15;
    const int m0 = blockIdx.y * 128;

    const __half* Qg = g_qh + ((size_t)bh * TT + m0) * DH;
    const __half* Kg = g_kh + (size_t)bh * TT * DH;
    const __half* Vg = g_vh + (size_t)bh * TT * DH;

    // ldmatrix lane offsets
    const int arow = (lane & 7) + ((lane >> 3) & 1) * 8, acol = (lane >> 4) * 4;
    const int brow = (lane & 7) + (lane >> 4) * 8,       bcol = ((lane >> 3) & 1) * 4;

    // ---- prologue: Q (1024 chunks) + K/V stage 0 via cp.async ----
#pragma unroll
    for (int j = 0; j < 4; j++) {
        int c = tid + 256 * j;
        int row = c >> 3, ch = c & 7;
        cpa16(s2u(Qs + row * FST + 4 * ch), Qg + row * 64 + 8 * ch);
    }
    {
        __half2* Kp = smh + QH2;
        __half2* Vp = Kp + KVH2;
#pragma unroll
        for (int j = 0; j < 2; j++) {
            int c = tid + 256 * j;
            int row = c >> 3, ch = c & 7;
            cpa16(s2u(Kp + row * FST + 4 * ch), Kg + row * 64 + 8 * ch);
            cpa16(s2u(Vp + row * FST + 4 * ch), Vg + row * 64 + 8 * ch);
        }
    }
    CP_COMMIT();

    float o[8][4];
#pragma unroll
    for (int dt = 0; dt < 8; dt++)
#pragma unroll
        for (int c = 0; c < 4; c++) o[dt][c] = 0.f;

    float mr0 = -1e30f, mr1 = -1e30f, l0 = 0.f, l1 = 0.f;
    const int   R   = wid * 16;
    const int   tq0 = m0 + R + g;
    const float SC2 = 0.125f * LOG2E;

    unsigned aQ[4][4];
    int st = 0;

    for (int n0k = 0; n0k < TT; n0k += 64) {
        if (n0k + 64 < TT) {
            __half2* Kp = smh + QH2 + (st ^ 1) * 2 * KVH2;
            __half2* Vp = Kp + KVH2;
            const __half* Kn = Kg + (size_t)(n0k + 64) * 64;
            const __half* Vn = Vg + (size_t)(n0k + 64) * 64;
#pragma unroll
            for (int j = 0; j < 2; j++) {
                int c = tid + 256 * j;
                int row = c >> 3, ch = c & 7;
                cpa16(s2u(Kp + row * FST + 4 * ch), Kn + row * 64 + 8 * ch);
                cpa16(s2u(Vp + row * FST + 4 * ch), Vn + row * 64 + 8 * ch);
            }
            CP_COMMIT();
            CP_WAIT(1);
        } else {
            CP_WAIT(0);
        }
        __syncthreads();

        __half2* Ksp = smh + QH2 + st * 2 * KVH2;
        __half2* Vsp = Ksp + KVH2;

        if (n0k == 0) {
#pragma unroll
            for (int kc = 0; kc < 4; kc++)
                ldsm4(aQ[kc], s2u(Qs + (R + arow) * FST + 8 * kc + acol));
        }

        // warp-uniform padding-mask check for this 64-key tile
        unsigned long long kw = 0;
        if (lane < 8)
            kw = *(const unsigned long long*)(kpm + (b << 10) + n0k + (lane << 3));
        const bool anymask = __any_sync(0xffffffffu, kw != 0ull);

        // ---- S = Q @ K^T ----
        float s[8][4];
#pragma unroll
        for (int nt = 0; nt < 8; nt++)
#pragma unroll
            for (int c = 0; c < 4; c++) s[nt][c] = 0.f;

#pragma unroll
        for (int kc = 0; kc < 4; kc++) {
#pragma unroll
            for (int np = 0; np < 4; np++) {
                unsigned bK[4];
                ldsm4(bK, s2u(Ksp + (16 * np + brow) * FST + 8 * kc + bcol));
                mma16(s[2 * np],     aQ[kc], bK[0], bK[1]);
                mma16(s[2 * np + 1], aQ[kc], bK[2], bK[3]);
            }
        }

        // ---- scale + attn-mask (pre-scaled, base-2 domain) ----
#pragma unroll
        for (int nt = 0; nt < 8; nt++) {
            int col = n0k + nt * 8 + 2 * t;
            float2 ma0 = *(const float2*)(g_am2 + (size_t)tq0 * TT + col);
            float2 ma1 = *(const float2*)(g_am2 + (size_t)(tq0 + 8) * TT + col);
            s[nt][0] = fmaf(s[nt][0], SC2, ma0.x);
            s[nt][1] = fmaf(s[nt][1], SC2, ma0.y);
            s[nt][2] = fmaf(s[nt][2], SC2, ma1.x);
            s[nt][3] = fmaf(s[nt][3], SC2, ma1.y);
        }

        // ---- online softmax ----
        float mx0 = -1e30f, mx1 = -1e30f;
#pragma unroll
        for (int nt = 0; nt < 8; nt++) {
            mx0 = fmaxf(mx0, fmaxf(s[nt][0], s[nt][1]));
            mx1 = fmaxf(mx1, fmaxf(s[nt][2], s[nt][3]));
        }
        mx0 = fmaxf(mx0, __shfl_xor_sync(0xffffffffu, mx0, 1));
        mx0 = fmaxf(mx0, __shfl_xor_sync(0xffffffffu, mx0, 2));
        mx1 = fmaxf(mx1, __shfl_xor_sync(0xffffffffu, mx1, 1));
        mx1 = fmaxf(mx1, __shfl_xor_sync(0xffffffffu, mx1, 2));

        float mn0 = fmaxf(mr0, mx0), mn1 = fmaxf(mr1, mx1);
        float al0 = exp2_fast(mr0 - mn0), al1 = exp2_fast(mr1 - mn1);
        mr0 = mn0; mr1 = mn1;

        float rs0 = 0.f, rs1 = 0.f;
        if (!anymask) {
#pragma unroll
            for (int nt = 0; nt < 8; nt++) {
                s[nt][0] = exp2_fast(s[nt][0] - mn0);
                s[nt][1] = exp2_fast(s[nt][1] - mn0);
                s[nt][2] = exp2_fast(s[nt][2] - mn1);
                s[nt][3] = exp2_fast(s[nt][3] - mn1);
                rs0 += s[nt][0] + s[nt][1];
                rs1 += s[nt][2] + s[nt][3];
            }
        } else {
#pragma unroll
            for (int nt = 0; nt < 8; nt++) {
                s[nt][0] = exp2_fast(s[nt][0] - mn0);
                s[nt][1] = exp2_fast(s[nt][1] - mn0);
                s[nt][2] = exp2_fast(s[nt][2] - mn1);
                s[nt][3] = exp2_fast(s[nt][3] - mn1);
                const unsigned char* kp = kpm + (b << 10) + n0k + (nt << 3) + (t << 1);
                if (kp[0]) { s[nt][0] = 0.f; s[nt][2] = 0.f; }
                if (kp[1]) { s[nt][1] = 0.f; s[nt][3] = 0.f; }
                rs0 += s[nt][0] + s[nt][1];
                rs1 += s[nt][2] + s[nt][3];
            }
        }
        rs0 += __shfl_xor_sync(0xffffffffu, rs0, 1);
        rs0 += __shfl_xor_sync(0xffffffffu, rs0, 2);
        rs1 += __shfl_xor_sync(0xffffffffu, rs1, 1);
        rs1 += __shfl_xor_sync(0xffffffffu, rs1, 2);
        l0 = l0 * al0 + rs0;
        l1 = l1 * al1 + rs1;

        if (!__all_sync(0xffffffffu, (al0 == 1.0f) & (al1 == 1.0f))) {
#pragma unroll
            for (int dt = 0; dt < 8; dt++) {
                o[dt][0] *= al0; o[dt][1] *= al0;
                o[dt][2] *= al1; o[dt][3] *= al1;
            }
        }

        // ---- O += P @ V  (P from registers: C-frag layout == A-frag layout) ----
#pragma unroll
        for (int kc = 0; kc < 4; kc++) {
            unsigned aP[4];
            aP[0] = h2u(pack2(s[2 * kc][0],     s[2 * kc][1]));
            aP[1] = h2u(pack2(s[2 * kc][2],     s[2 * kc][3]));
            aP[2] = h2u(pack2(s[2 * kc + 1][0], s[2 * kc + 1][1]));
            aP[3] = h2u(pack2(s[2 * kc + 1][2], s[2 * kc + 1][3]));
#pragma unroll
            for (int dp = 0; dp < 4; dp++) {
                unsigned bV[4];
                ldsm4t(bV, s2u(Vsp + (16 * kc + arow) * FST + 8 * dp + acol));
                mma16(o[2 * dp],     aP, bV[0], bV[1]);
                mma16(o[2 * dp + 1], aP, bV[2], bV[3]);
            }
        }
        __syncthreads();
        st ^= 1;
    }

    // ---- normalize + write fp16 [b, t, h*64+d] ----
    float inv0 = 1.f / l0, inv1 = 1.f / l1;
#pragma unroll
    for (int dt = 0; dt < 8; dt++) {
        int col = h * 64 + dt * 8 + 2 * t;
        *(__half2*)&g_ao16[(size_t)(b * TT + tq0) * EMB + col]
            = pack2(o[dt][0] * inv0, o[dt][1] * inv0);
        *(__half2*)&g_ao16[(size_t)(b * TT + tq0 + 8) * EMB + col]
            = pack2(o[dt][2] * inv1, o[dt][3] * inv1);
    }
}

// ============================================================================
extern "C" void kernel_launch(void* const* d_in, const int* in_sizes, int n_in,
                              void* d_out, int out_size)
{
    (void)in_sizes; (void)n_in; (void)out_size;
    const float*         query = (const float*)d_in[0];
    const float*         key   = (const float*)d_in[1];
    const float*         value = (const float*)d_in[2];
    const unsigned char* kpm   = (const unsigned char*)d_in[3];
    const float*         amask = (const float*)d_in[4];
    const float*         win   = (const float*)d_in[5];
    const float*         bin   = (const float*)d_in[6];
    const float*         wout  = (const float*)d_in[7];
    const float*         bout  = (const float*)d_in[8];
    float*               out   = (float*)d_out;

    __half *pq16, *pk16, *pv16, *pw16, *pwo16, *pqh, *pkh, *pvh, *pao16;
    cudaGetSymbolAddress((void**)&pq16,  g_q16);
    cudaGetSymbolAddress((void**)&pk16,  g_k16);
    cudaGetSymbolAddress((void**)&pv16,  g_v16);
    cudaGetSymbolAddress((void**)&pw16,  g_w16);
    cudaGetSymbolAddress((void**)&pwo16, g_wo16);
    cudaGetSymbolAddress((void**)&pqh,   g_qh);
    cudaGetSymbolAddress((void**)&pkh,   g_kh);
    cudaGetSymbolAddress((void**)&pvh,   g_vh);
    cudaGetSymbolAddress((void**)&pao16, g_ao16);

    // ---- prep: fp32 -> fp16 conversions + mask pre-scale ----
    f2h<<<NTOK*EMB/2048, 256>>>(query, pq16);
    f2h<<<NTOK*EMB/2048, 256>>>(key,   pk16);
    f2h<<<NTOK*EMB/2048, 256>>>(value, pv16);
    f2h<<<3*EMB*EMB/2048, 256>>>(win,  pw16);
    f2h<<<EMB*EMB/2048, 256>>>(wout,   pwo16);
    prep_mask<<<TT*TT/1024, 256>>>(amask);

    // ---- Q/K/V projections (one launch, grid.z = 3) ----
    gemm_fp16<<<dim3(8, 64, 3), 256>>>(pq16, pk16, pv16, pw16, bin,
                                       pqh, pkh, pvh, nullptr, 1);

    // ---- flash attention ----
    cudaFuncSetAttribute(flash_fp16,
                         cudaFuncAttributeMaxDynamicSharedMemorySize, FLASH_SMEM);
    flash_fp16<<<dim3(BHD, TT / 128), 256, FLASH_SMEM>>>(kpm);

    // ---- output projection -> d_out (fp32) ----
    gemm_fp16<<<dim3(8, 64, 1), 256>>>(pao16, pao16, pao16, pwo16, bout,
                                       nullptr, nullptr, nullptr, out, 0);
}

// round 15
// speedup vs baseline: 2.4122x; 1.0239x over previous
#include <cuda_runtime.h>
#include <cuda_fp16.h>
#include <stdint.h>
#include <math.h>

// Problem constants
#define BQ    8
#define TT    1024
#define EMB   1024
#define NH    16
#define DH    64
#define NTOK  (BQ*TT)      // 8192
#define BHD   (BQ*NH)      // 128

#define LOG2E 1.4426950408889634f

// -------- scratch (static device arrays: no allocation APIs allowed) --------
__device__ __half g_q16 [NTOK*EMB];
__device__ __half g_k16 [NTOK*EMB];
__device__ __half g_v16 [NTOK*EMB];
__device__ __half g_w16 [3*EMB*EMB];
__device__ __half g_wo16[EMB*EMB];
__device__ __half g_qh  [BHD*TT*DH];
__device__ __half g_kh  [BHD*TT*DH];
__device__ __half g_vh  [BHD*TT*DH];
__device__ __half g_ao16[NTOK*EMB];
__device__ float  g_am8 [TT*TT];        // amask * 8  (so (QK + am8)*SC2 = base-2 score)

// ---------------------------------------------------------------------------
// helpers
// ---------------------------------------------------------------------------
__device__ __forceinline__ unsigned h2u(__half2 h) { return *(unsigned*)&h; }
__device__ __forceinline__ __half2 pack2(float x, float y) { return __floats2half2_rn(x, y); }

__device__ __forceinline__ void mma16(float* d, const unsigned* a, unsigned b0, unsigned b1) {
    asm volatile(
        "mma.sync.aligned.m16n8k16.row.col.f32.f16.f16.f32 "
        "{%0,%1,%2,%3}, {%4,%5,%6,%7}, {%8,%9}, {%0,%1,%2,%3};\n"
        : "+f"(d[0]), "+f"(d[1]), "+f"(d[2]), "+f"(d[3])
        : "r"(a[0]), "r"(a[1]), "r"(a[2]), "r"(a[3]), "r"(b0), "r"(b1));
}

__device__ __forceinline__ uint32_t s2u(const void* p) {
    return (uint32_t)__cvta_generic_to_shared(p);
}
__device__ __forceinline__ void ldsm4(unsigned* r, uint32_t addr) {
    asm volatile("ldmatrix.sync.aligned.m8n8.x4.shared.b16 {%0,%1,%2,%3}, [%4];"
                 : "=r"(r[0]), "=r"(r[1]), "=r"(r[2]), "=r"(r[3]) : "r"(addr));
}
__device__ __forceinline__ void ldsm4t(unsigned* r, uint32_t addr) {
    asm volatile("ldmatrix.sync.aligned.m8n8.x4.trans.shared.b16 {%0,%1,%2,%3}, [%4];"
                 : "=r"(r[0]), "=r"(r[1]), "=r"(r[2]), "=r"(r[3]) : "r"(addr));
}
__device__ __forceinline__ void cpa16(uint32_t dst, const void* src) {
    asm volatile("cp.async.ca.shared.global [%0], [%1], 16;" :: "r"(dst), "l"(src));
}
#define CP_COMMIT() asm volatile("cp.async.commit_group;")
#define CP_WAIT(n)  asm volatile("cp.async.wait_group %0;" :: "n"(n))

// FMA-only exp2 (no MUFU). y <= 0 expected; clamped below -126 -> ~0.
__device__ __forceinline__ float exp2_fast(float y) {
    y = fmaxf(y, -126.0f);
    float r  = y + 12582912.0f;
    int   n  = __float_as_int(r) - 0x4B400000;
    float f  = y - (r - 12582912.0f);
    float p  =            1.3333558146428443e-3f;
    p = fmaf(p, f,        9.6181291076284771e-3f);
    p = fmaf(p, f,        5.5504108664821580e-2f);
    p = fmaf(p, f,        2.4022650695910072e-1f);
    p = fmaf(p, f,        6.9314718055994531e-1f);
    p = fmaf(p, f,        1.0f);
    return p * __int_as_float((n + 127) << 23);
}

// ---------------------------------------------------------------------------
// fused prep: fp32->fp16 for 5 tensors (grid.y = 0..4), mask*8 (grid.y = 5)
// ---------------------------------------------------------------------------
__global__ void prep_all(const float* __restrict__ q, const float* __restrict__ k,
                         const float* __restrict__ v, const float* __restrict__ win,
                         const float* __restrict__ wout, const float* __restrict__ am,
                         __half* __restrict__ q16, __half* __restrict__ k16,
                         __half* __restrict__ v16, __half* __restrict__ w16,
                         __half* __restrict__ wo16)
{
    int r = blockIdx.y, bx = blockIdx.x;
    if (r == 5) {
        if (bx >= TT*TT/1024) return;
        int i = (bx * 256 + threadIdx.x) * 4;
        float4 m = *(const float4*)(am + i);
        m.x *= 8.f; m.y *= 8.f; m.z *= 8.f; m.w *= 8.f;
        *(float4*)&g_am8[i] = m;
        return;
    }
    const float* src; __half* dst; int nb;
    switch (r) {
        case 0: src = q;    dst = q16;  nb = NTOK*EMB/2048;  break;
        case 1: src = k;    dst = k16;  nb = NTOK*EMB/2048;  break;
        case 2: src = v;    dst = v16;  nb = NTOK*EMB/2048;  break;
        case 3: src = win;  dst = w16;  nb = 3*EMB*EMB/2048; break;
        default: src = wout; dst = wo16; nb = EMB*EMB/2048;  break;
    }
    if (bx >= nb) return;
    int i = (bx * 256 + threadIdx.x) * 8;
    float4 a = *(const float4*)(src + i);
    float4 b = *(const float4*)(src + i + 4);
    __half2 h[4] = { pack2(a.x, a.y), pack2(a.z, a.w), pack2(b.x, b.y), pack2(b.z, b.w) };
    *(uint4*)(dst + i) = *(uint4*)h;
}

// ---------------------------------------------------------------------------
// fp16 GEMM (fp32 accum): C = A*B^T + bias. M=8192 N=1024 K=1024.
// 128x128 tile, BK=32, 256 thr, warp tile 32x64, cp.async 3-stage, ldmatrix.
// grid.z selects A/C (QKV merged). mode 0: fp32 row-major; 1: [b,h,t,d] fp16.
// ---------------------------------------------------------------------------
#define GST  20
#define SSTG (128 * GST)                 // half2 per stage per matrix
#define GSMEM (6 * SSTG * 4)             // 61440 B (3 stages x A,B)

__global__ __launch_bounds__(256, 2)
void gemm_fp16(const __half* __restrict__ A0, const __half* __restrict__ A1,
               const __half* __restrict__ A2, const __half* __restrict__ Bw,
               const float* __restrict__ bias0,
               __half* __restrict__ H0, __half* __restrict__ H1, __half* __restrict__ H2,
               float* __restrict__ Cf, int mode)
{
    extern __shared__ __half2 gsm[];
    __half2* Asm = gsm;                  // 3 stages
    __half2* Bsm = gsm + 3 * SSTG;

    const int z = blockIdx.z;
    const __half* A    = (z == 0) ? A0 : (z == 1) ? A1 : A2;
    const __half* B    = Bw + (size_t)z * 1024 * 1024;
    const float*  bias = bias0 + z * 1024;
    __half*       H    = (z == 0) ? H0 : (z == 1) ? H1 : H2;

    const int tid  = threadIdx.x;
    const int lane = tid & 31, wid = tid >> 5;
    const int g = lane >> 2, t = lane & 3;
    const int wm = (wid >> 1) * 32, wn = (wid & 1) * 64;
    const int m0 = blockIdx.y * 128, n0 = blockIdx.x * 128;

    const int rpat = (lane >> 3) + (((lane >> 2) & 1) << 2);   // 0,4,1,5,2,6,3,7
    const int chnk = lane & 3;
    const int lr   = (wid << 3) + rpat;

    const int arow = (lane & 7) + ((lane >> 3) & 1) * 8, acol = (lane >> 4) * 4;
    const int brow = (lane & 7) + (lane >> 4) * 8,       bcol = ((lane >> 3) & 1) * 4;

    float acc[2][8][4];
#pragma unroll
    for (int mt = 0; mt < 2; mt++)
#pragma unroll
        for (int nt = 0; nt < 8; nt++)
#pragma unroll
            for (int c = 0; c < 4; c++) acc[mt][nt][c] = 0.f;

    // prologue: stages 0 (kb=0) and 1 (kb=32)
#pragma unroll
    for (int sg = 0; sg < 2; sg++) {
#pragma unroll
        for (int j = 0; j < 2; j++) {
            int r = lr + (j << 6);
            cpa16(s2u(&Asm[sg * SSTG + r * GST + (chnk << 2)]),
                  A + ((size_t)(m0 + r) << 10) + 32 * sg + (chnk << 3));
            cpa16(s2u(&Bsm[sg * SSTG + r * GST + (chnk << 2)]),
                  B + ((size_t)(n0 + r) << 10) + 32 * sg + (chnk << 3));
        }
        CP_COMMIT();
    }

    int st = 0;
    for (int kb = 0; kb < 1024; kb += 32) {
        if (kb == 1024 - 32) { CP_WAIT(0); } else { CP_WAIT(1); }
        __syncthreads();

        if (kb + 64 < 1024) {
            int stp = st + 2; if (stp >= 3) stp -= 3;
#pragma unroll
            for (int j = 0; j < 2; j++) {
                int r = lr + (j << 6);
                cpa16(s2u(&Asm[stp * SSTG + r * GST + (chnk << 2)]),
                      A + ((size_t)(m0 + r) << 10) + kb + 64 + (chnk << 3));
                cpa16(s2u(&Bsm[stp * SSTG + r * GST + (chnk << 2)]),
                      B + ((size_t)(n0 + r) << 10) + kb + 64 + (chnk << 3));
            }
            CP_COMMIT();
        }

        const __half2* As = Asm + st * SSTG;
        const __half2* Bs = Bsm + st * SSTG;
#pragma unroll
        for (int kc = 0; kc < 2; kc++) {
            unsigned aF[2][4], bF[4][4];
#pragma unroll
            for (int mt = 0; mt < 2; mt++)
                ldsm4(aF[mt], s2u(&As[(wm + 16 * mt + arow) * GST + 8 * kc + acol]));
#pragma unroll
            for (int np = 0; np < 4; np++)
                ldsm4(bF[np], s2u(&Bs[(wn + 16 * np + brow) * GST + 8 * kc + bcol]));
#pragma unroll
            for (int mt = 0; mt < 2; mt++)
#pragma unroll
                for (int np = 0; np < 4; np++) {
                    mma16(acc[mt][2 * np],     aF[mt], bF[np][0], bF[np][1]);
                    mma16(acc[mt][2 * np + 1], aF[mt], bF[np][2], bF[np][3]);
                }
        }
        st++; if (st >= 3) st -= 3;
    }

#pragma unroll
    for (int nt = 0; nt < 8; nt++) {
        int n = n0 + wn + nt * 8 + 2 * t;
        float bv0 = bias[n], bv1 = bias[n + 1];
#pragma unroll
        for (int mt = 0; mt < 2; mt++) {
            int r = m0 + wm + mt * 16 + g;
            if (mode == 0) {
                *(float2*)&Cf[(size_t)r * 1024 + n]
                    = make_float2(acc[mt][nt][0] + bv0, acc[mt][nt][1] + bv1);
                *(float2*)&Cf[(size_t)(r + 8) * 1024 + n]
                    = make_float2(acc[mt][nt][2] + bv0, acc[mt][nt][3] + bv1);
            } else {
                int h = n >> 6, d = n & 63;
                int bb = r >> 10, tq = r & 1023;
                *(__half2*)&H[(size_t)((bb * NH + h) * TT + tq) * DH + d]
                    = pack2(acc[mt][nt][0] + bv0, acc[mt][nt][1] + bv1);
                *(__half2*)&H[(size_t)((bb * NH + h) * TT + tq + 8) * DH + d]
                    = pack2(acc[mt][nt][2] + bv0, acc[mt][nt][3] + bv1);
            }
        }
    }
}

// ---------------------------------------------------------------------------
// Flash attention, fp16 MMA (fp32 accum). BM=128, BN=64, Dh=64.
// 256 thr / 8 warps; warp w owns rows [16w,16w+16) -> quad-local softmax.
// cp.async 2-stage K/V; ldmatrix frags; P in registers.
// Mask tile (g_am8) loads ARE the S-accumulator init -> overlapped with QK mma.
// ---------------------------------------------------------------------------
#define FST 36
#define QH2  (128 * FST)
#define KVH2 (64 * FST)
#define FLASH_SMEM ((QH2 + 4 * KVH2) * 4)   // 55296 B

__global__ __launch_bounds__(256, 2)
void flash_fp16(const unsigned char* __restrict__ kpm)
{
    extern __shared__ __half2 smh[];
    __half2* Qs = smh;

    const int tid  = threadIdx.x;
    const int lane = tid & 31, wid = tid >> 5;
    const int g = lane >> 2, t = lane & 3;
    const int bh = blockIdx.x, b = bh >> 4, h = bh & 15;
    const int m0 = blockIdx.y * 128;

    const __half* Qg = g_qh + ((size_t)bh * TT + m0) * DH;
    const __half* Kg = g_kh + (size_t)bh * TT * DH;
    const __half* Vg = g_vh + (size_t)bh * TT * DH;

    const int arow = (lane & 7) + ((lane >> 3) & 1) * 8, acol = (lane >> 4) * 4;
    const int brow = (lane & 7) + (lane >> 4) * 8,       bcol = ((lane >> 3) & 1) * 4;

    // ---- prologue: Q + K/V stage 0 via cp.async ----
#pragma unroll
    for (int j = 0; j < 4; j++) {
        int c = tid + 256 * j;
        int row = c >> 3, ch = c & 7;
        cpa16(s2u(Qs + row * FST + 4 * ch), Qg + row * 64 + 8 * ch);
    }
    {
        __half2* Kp = smh + QH2;
        __half2* Vp = Kp + KVH2;
#pragma unroll
        for (int j = 0; j < 2; j++) {
            int c = tid + 256 * j;
            int row = c >> 3, ch = c & 7;
            cpa16(s2u(Kp + row * FST + 4 * ch), Kg + row * 64 + 8 * ch);
            cpa16(s2u(Vp + row * FST + 4 * ch), Vg + row * 64 + 8 * ch);
        }
    }
    CP_COMMIT();

    float o[8][4];
#pragma unroll
    for (int dt = 0; dt < 8; dt++)
#pragma unroll
        for (int c = 0; c < 4; c++) o[dt][c] = 0.f;

    float mr0 = -1e30f, mr1 = -1e30f, l0 = 0.f, l1 = 0.f;
    const int   R   = wid * 16;
    const int   tq0 = m0 + R + g;
    const float SC2 = 0.125f * LOG2E;

    const float* am0 = g_am8 + (size_t)tq0 * TT;
    const float* am8 = am0 + 8 * TT;

    unsigned aQ[4][4];
    int st = 0;

    for (int n0k = 0; n0k < TT; n0k += 64) {
        if (n0k + 64 < TT) {
            __half2* Kp = smh + QH2 + (st ^ 1) * 2 * KVH2;
            __half2* Vp = Kp + KVH2;
            const __half* Kn = Kg + (size_t)(n0k + 64) * 64;
            const __half* Vn = Vg + (size_t)(n0k + 64) * 64;
#pragma unroll
            for (int j = 0; j < 2; j++) {
                int c = tid + 256 * j;
                int row = c >> 3, ch = c & 7;
                cpa16(s2u(Kp + row * FST + 4 * ch), Kn + row * 64 + 8 * ch);
                cpa16(s2u(Vp + row * FST + 4 * ch), Vn + row * 64 + 8 * ch);
            }
            CP_COMMIT();
            CP_WAIT(1);
        } else {
            CP_WAIT(0);
        }
        __syncthreads();

        __half2* Ksp = smh + QH2 + st * 2 * KVH2;
        __half2* Vsp = Ksp + KVH2;

        if (n0k == 0) {
#pragma unroll
            for (int kc = 0; kc < 4; kc++)
                ldsm4(aQ[kc], s2u(Qs + (R + arow) * FST + 8 * kc + acol));
        }

        // warp-uniform padding-mask check for this 64-key tile
        unsigned long long kw = 0;
        if (lane < 8)
            kw = *(const unsigned long long*)(kpm + (b << 10) + n0k + (lane << 3));
        const bool anymask = __any_sync(0xffffffffu, kw != 0ull);

        // ---- S init = mask tile (am*8); QK mma accumulates on top ----
        float s[8][4];
#pragma unroll
        for (int nt = 0; nt < 8; nt++) {
            int col = n0k + nt * 8 + 2 * t;
            *(float2*)&s[nt][0] = *(const float2*)(am0 + col);
            *(float2*)&s[nt][2] = *(const float2*)(am8 + col);
        }

#pragma unroll
        for (int kc = 0; kc < 4; kc++) {
#pragma unroll
            for (int np = 0; np < 4; np++) {
                unsigned bK[4];
                ldsm4(bK, s2u(Ksp + (16 * np + brow) * FST + 8 * kc + bcol));
                mma16(s[2 * np],     aQ[kc], bK[0], bK[1]);
                mma16(s[2 * np + 1], aQ[kc], bK[2], bK[3]);
            }
        }

        // ---- online softmax (raw-domain max, scale folded into exp arg) ----
        float mx0 = -1e30f, mx1 = -1e30f;
#pragma unroll
        for (int nt = 0; nt < 8; nt++) {
            mx0 = fmaxf(mx0, fmaxf(s[nt][0], s[nt][1]));
            mx1 = fmaxf(mx1, fmaxf(s[nt][2], s[nt][3]));
        }
        mx0 = fmaxf(mx0, __shfl_xor_sync(0xffffffffu, mx0, 1));
        mx0 = fmaxf(mx0, __shfl_xor_sync(0xffffffffu, mx0, 2));
        mx1 = fmaxf(mx1, __shfl_xor_sync(0xffffffffu, mx1, 1));
        mx1 = fmaxf(mx1, __shfl_xor_sync(0xffffffffu, mx1, 2));

        float mn0 = fmaxf(mr0, mx0 * SC2), mn1 = fmaxf(mr1, mx1 * SC2);
        float al0 = exp2_fast(mr0 - mn0), al1 = exp2_fast(mr1 - mn1);
        mr0 = mn0; mr1 = mn1;

        float rs0 = 0.f, rs1 = 0.f;
        if (!anymask) {
#pragma unroll
            for (int nt = 0; nt < 8; nt++) {
                s[nt][0] = exp2_fast(fmaf(s[nt][0], SC2, -mn0));
                s[nt][1] = exp2_fast(fmaf(s[nt][1], SC2, -mn0));
                s[nt][2] = exp2_fast(fmaf(s[nt][2], SC2, -mn1));
                s[nt][3] = exp2_fast(fmaf(s[nt][3], SC2, -mn1));
                rs0 += s[nt][0] + s[nt][1];
                rs1 += s[nt][2] + s[nt][3];
            }
        } else {
#pragma unroll
            for (int nt = 0; nt < 8; nt++) {
                s[nt][0] = exp2_fast(fmaf(s[nt][0], SC2, -mn0));
                s[nt][1] = exp2_fast(fmaf(s[nt][1], SC2, -mn0));
                s[nt][2] = exp2_fast(fmaf(s[nt][2], SC2, -mn1));
                s[nt][3] = exp2_fast(fmaf(s[nt][3], SC2, -mn1));
                const unsigned char* kp = kpm + (b << 10) + n0k + (nt << 3) + (t << 1);
                if (kp[0]) { s[nt][0] = 0.f; s[nt][2] = 0.f; }
                if (kp[1]) { s[nt][1] = 0.f; s[nt][3] = 0.f; }
                rs0 += s[nt][0] + s[nt][1];
                rs1 += s[nt][2] + s[nt][3];
            }
        }
        rs0 += __shfl_xor_sync(0xffffffffu, rs0, 1);
        rs0 += __shfl_xor_sync(0xffffffffu, rs0, 2);
        rs1 += __shfl_xor_sync(0xffffffffu, rs1, 1);
        rs1 += __shfl_xor_sync(0xffffffffu, rs1, 2);
        l0 = l0 * al0 + rs0;
        l1 = l1 * al1 + rs1;

        if (!__all_sync(0xffffffffu, (al0 == 1.0f) & (al1 == 1.0f))) {
#pragma unroll
            for (int dt = 0; dt < 8; dt++) {
                o[dt][0] *= al0; o[dt][1] *= al0;
                o[dt][2] *= al1; o[dt][3] *= al1;
            }
        }

        // ---- O += P @ V  (P from registers) ----
#pragma unroll
        for (int kc = 0; kc < 4; kc++) {
            unsigned aP[4];
            aP[0] = h2u(pack2(s[2 * kc][0],     s[2 * kc][1]));
            aP[1] = h2u(pack2(s[2 * kc][2],     s[2 * kc][3]));
            aP[2] = h2u(pack2(s[2 * kc + 1][0], s[2 * kc + 1][1]));
            aP[3] = h2u(pack2(s[2 * kc + 1][2], s[2 * kc + 1][3]));
#pragma unroll
            for (int dp = 0; dp < 4; dp++) {
                unsigned bV[4];
                ldsm4t(bV, s2u(Vsp + (16 * kc + arow) * FST + 8 * dp + acol));
                mma16(o[2 * dp],     aP, bV[0], bV[1]);
                mma16(o[2 * dp + 1], aP, bV[2], bV[3]);
            }
        }
        __syncthreads();
        st ^= 1;
    }

    // ---- normalize + write fp16 [b, t, h*64+d] ----
    float inv0 = 1.f / l0, inv1 = 1.f / l1;
#pragma unroll
    for (int dt = 0; dt < 8; dt++) {
        int col = h * 64 + dt * 8 + 2 * t;
        *(__half2*)&g_ao16[(size_t)(b * TT + tq0) * EMB + col]
            = pack2(o[dt][0] * inv0, o[dt][1] * inv0);
        *(__half2*)&g_ao16[(size_t)(b * TT + tq0 + 8) * EMB + col]
            = pack2(o[dt][2] * inv1, o[dt][3] * inv1);
    }
}

// ============================================================================
extern "C" void kernel_launch(void* const* d_in, const int* in_sizes, int n_in,
                              void* d_out, int out_size)
{
    (void)in_sizes; (void)n_in; (void)out_size;
    const float*         query = (const float*)d_in[0];
    const float*         key   = (const float*)d_in[1];
    const float*         value = (const float*)d_in[2];
    const unsigned char* kpm   = (const unsigned char*)d_in[3];
    const float*         amask = (const float*)d_in[4];
    const float*         win   = (const float*)d_in[5];
    const float*         bin   = (const float*)d_in[6];
    const float*         wout  = (const float*)d_in[7];
    const float*         bout  = (const float*)d_in[8];
    float*               out   = (float*)d_out;

    __half *pq16, *pk16, *pv16, *pw16, *pwo16, *pqh, *pkh, *pvh, *pao16;
    cudaGetSymbolAddress((void**)&pq16,  g_q16);
    cudaGetSymbolAddress((void**)&pk16,  g_k16);
    cudaGetSymbolAddress((void**)&pv16,  g_v16);
    cudaGetSymbolAddress((void**)&pw16,  g_w16);
    cudaGetSymbolAddress((void**)&pwo16, g_wo16);
    cudaGetSymbolAddress((void**)&pqh,   g_qh);
    cudaGetSymbolAddress((void**)&pkh,   g_kh);
    cudaGetSymbolAddress((void**)&pvh,   g_vh);
    cudaGetSymbolAddress((void**)&pao16, g_ao16);

    // ---- fused prep (one launch) ----
    prep_all<<<dim3(4096, 6), 256>>>(query, key, value, win, wout, amask,
                                     pq16, pk16, pv16, pw16, pwo16);

    // ---- Q/K/V projections (one launch, grid.z = 3), 3-stage pipeline ----
    cudaFuncSetAttribute(gemm_fp16,
                         cudaFuncAttributeMaxDynamicSharedMemorySize, GSMEM);
    gemm_fp16<<<dim3(8, 64, 3), 256, GSMEM>>>(pq16, pk16, pv16, pw16, bin,
                                              pqh, pkh, pvh, nullptr, 1);

    // ---- flash attention ----
    cudaFuncSetAttribute(flash_fp16,
                         cudaFuncAttributeMaxDynamicSharedMemorySize, FLASH_SMEM);
    flash_fp16<<<dim3(BHD, TT / 128), 256, FLASH_SMEM>>>(kpm);

    // ---- output projection -> d_out (fp32) ----
    gemm_fp16<<<dim3(8, 64, 1), 256, GSMEM>>>(pao16, pao16, pao16, pwo16, bout,
                                              nullptr, nullptr, nullptr, out, 0);
}

// round 16
// speedup vs baseline: 2.6389x; 1.0940x over previous
#include <cuda_runtime.h>
#include <cuda_fp16.h>
#include <stdint.h>
#include <math.h>

// Problem constants
#define BQ    8
#define TT    1024
#define EMB   1024
#define NH    16
#define DH    64
#define NTOK  (BQ*TT)      // 8192
#define BHD   (BQ*NH)      // 128

#define LOG2E 1.4426950408889634f

// -------- scratch (static device arrays: no allocation APIs allowed) --------
__device__ __half g_q16 [NTOK*EMB];
__device__ __half g_k16 [NTOK*EMB];
__device__ __half g_v16 [NTOK*EMB];
__device__ __half g_w16 [3*EMB*EMB];
__device__ __half g_wo16[EMB*EMB];
__device__ __half g_qh  [BHD*TT*DH];
__device__ __half g_kh  [BHD*TT*DH];
__device__ __half g_vh  [BHD*TT*DH];
__device__ __half g_ao16[NTOK*EMB];
__device__ float  g_am8 [TT*TT];        // amask * 8  (so (QK + am8)*SC2 = base-2 score)

// ---------------------------------------------------------------------------
// helpers
// ---------------------------------------------------------------------------
__device__ __forceinline__ unsigned h2u(__half2 h) { return *(unsigned*)&h; }
__device__ __forceinline__ __half2 pack2(float x, float y) { return __floats2half2_rn(x, y); }

__device__ __forceinline__ void mma16(float* d, const unsigned* a, unsigned b0, unsigned b1) {
    asm volatile(
        "mma.sync.aligned.m16n8k16.row.col.f32.f16.f16.f32 "
        "{%0,%1,%2,%3}, {%4,%5,%6,%7}, {%8,%9}, {%0,%1,%2,%3};\n"
        : "+f"(d[0]), "+f"(d[1]), "+f"(d[2]), "+f"(d[3])
        : "r"(a[0]), "r"(a[1]), "r"(a[2]), "r"(a[3]), "r"(b0), "r"(b1));
}

__device__ __forceinline__ uint32_t s2u(const void* p) {
    return (uint32_t)__cvta_generic_to_shared(p);
}
__device__ __forceinline__ void ldsm4(unsigned* r, uint32_t addr) {
    asm volatile("ldmatrix.sync.aligned.m8n8.x4.shared.b16 {%0,%1,%2,%3}, [%4];"
                 : "=r"(r[0]), "=r"(r[1]), "=r"(r[2]), "=r"(r[3]) : "r"(addr));
}
__device__ __forceinline__ void ldsm4t(unsigned* r, uint32_t addr) {
    asm volatile("ldmatrix.sync.aligned.m8n8.x4.trans.shared.b16 {%0,%1,%2,%3}, [%4];"
                 : "=r"(r[0]), "=r"(r[1]), "=r"(r[2]), "=r"(r[3]) : "r"(addr));
}
__device__ __forceinline__ void cpa16(uint32_t dst, const void* src) {
    asm volatile("cp.async.ca.shared.global [%0], [%1], 16;" :: "r"(dst), "l"(src));
}
#define CP_COMMIT() asm volatile("cp.async.commit_group;")
#define CP_WAIT(n)  asm volatile("cp.async.wait_group %0;" :: "n"(n))

// FMA-only exp2 (no MUFU). y <= 0 expected; clamped below -126 -> ~0.
__device__ __forceinline__ float exp2_fast(float y) {
    y = fmaxf(y, -126.0f);
    float r  = y + 12582912.0f;
    int   n  = __float_as_int(r) - 0x4B400000;
    float f  = y - (r - 12582912.0f);
    float p  =            1.3333558146428443e-3f;
    p = fmaf(p, f,        9.6181291076284771e-3f);
    p = fmaf(p, f,        5.5504108664821580e-2f);
    p = fmaf(p, f,        2.4022650695910072e-1f);
    p = fmaf(p, f,        6.9314718055994531e-1f);
    p = fmaf(p, f,        1.0f);
    return p * __int_as_float((n + 127) << 23);
}

// ---------------------------------------------------------------------------
// fused prep: fp32->fp16 for 5 tensors (grid.y = 0..4), mask*8 (grid.y = 5)
// ---------------------------------------------------------------------------
__global__ void prep_all(const float* __restrict__ q, const float* __restrict__ k,
                         const float* __restrict__ v, const float* __restrict__ win,
                         const float* __restrict__ wout, const float* __restrict__ am,
                         __half* __restrict__ q16, __half* __restrict__ k16,
                         __half* __restrict__ v16, __half* __restrict__ w16,
                         __half* __restrict__ wo16)
{
    int r = blockIdx.y, bx = blockIdx.x;
    if (r == 5) {
        if (bx >= TT*TT/1024) return;
        int i = (bx * 256 + threadIdx.x) * 4;
        float4 m = *(const float4*)(am + i);
        m.x *= 8.f; m.y *= 8.f; m.z *= 8.f; m.w *= 8.f;
        *(float4*)&g_am8[i] = m;
        return;
    }
    const float* src; __half* dst; int nb;
    switch (r) {
        case 0: src = q;    dst = q16;  nb = NTOK*EMB/2048;  break;
        case 1: src = k;    dst = k16;  nb = NTOK*EMB/2048;  break;
        case 2: src = v;    dst = v16;  nb = NTOK*EMB/2048;  break;
        case 3: src = win;  dst = w16;  nb = 3*EMB*EMB/2048; break;
        default: src = wout; dst = wo16; nb = EMB*EMB/2048;  break;
    }
    if (bx >= nb) return;
    int i = (bx * 256 + threadIdx.x) * 8;
    float4 a = *(const float4*)(src + i);
    float4 b = *(const float4*)(src + i + 4);
    __half2 h[4] = { pack2(a.x, a.y), pack2(a.z, a.w), pack2(b.x, b.y), pack2(b.z, b.w) };
    *(uint4*)(dst + i) = *(uint4*)h;
}

// ---------------------------------------------------------------------------
// fp16 GEMM (fp32 accum): C = A*B^T + bias. M=8192 N=1024 K=1024.
// 128x128 block tile, BK=32, 128 thr / 4 warps, WARP TILE 64x64,
// cp.async 3-stage, ldmatrix. LDSM/MMA = 0.25 (was 0.375).
// grid.z selects A/C (QKV merged). mode 0: fp32 row-major; 1: [b,h,t,d] fp16.
// ---------------------------------------------------------------------------
#define GST  20
#define SSTG (128 * GST)                 // half2 per stage per matrix
#define GSMEM (6 * SSTG * 4)             // 61440 B (3 stages x A,B)

__global__ __launch_bounds__(128, 2)
void gemm_fp16(const __half* __restrict__ A0, const __half* __restrict__ A1,
               const __half* __restrict__ A2, const __half* __restrict__ Bw,
               const float* __restrict__ bias0,
               __half* __restrict__ H0, __half* __restrict__ H1, __half* __restrict__ H2,
               float* __restrict__ Cf, int mode)
{
    extern __shared__ __half2 gsm[];
    __half2* Asm = gsm;                  // 3 stages
    __half2* Bsm = gsm + 3 * SSTG;

    const int z = blockIdx.z;
    const __half* A    = (z == 0) ? A0 : (z == 1) ? A1 : A2;
    const __half* B    = Bw + (size_t)z * 1024 * 1024;
    const float*  bias = bias0 + z * 1024;
    __half*       H    = (z == 0) ? H0 : (z == 1) ? H1 : H2;

    const int tid  = threadIdx.x;
    const int lane = tid & 31, wid = tid >> 5;      // 4 warps
    const int g = lane >> 2, t = lane & 3;
    const int wm = (wid >> 1) * 64, wn = (wid & 1) * 64;
    const int m0 = blockIdx.y * 128, n0 = blockIdx.x * 128;

    const int rpat = (lane >> 3) + (((lane >> 2) & 1) << 2);   // 0,4,1,5,2,6,3,7
    const int chnk = lane & 3;
    const int lr   = (wid << 3) + rpat;                         // rows 0..31

    const int arow = (lane & 7) + ((lane >> 3) & 1) * 8, acol = (lane >> 4) * 4;
    const int brow = (lane & 7) + (lane >> 4) * 8,       bcol = ((lane >> 3) & 1) * 4;

    float acc[4][8][4];
#pragma unroll
    for (int mt = 0; mt < 4; mt++)
#pragma unroll
        for (int nt = 0; nt < 8; nt++)
#pragma unroll
            for (int c = 0; c < 4; c++) acc[mt][nt][c] = 0.f;

    // prologue: stages 0 (kb=0) and 1 (kb=32); 128 rows via 4 j-iters
#pragma unroll
    for (int sg = 0; sg < 2; sg++) {
#pragma unroll
        for (int j = 0; j < 4; j++) {
            int r = lr + (j << 5);
            cpa16(s2u(&Asm[sg * SSTG + r * GST + (chnk << 2)]),
                  A + ((size_t)(m0 + r) << 10) + 32 * sg + (chnk << 3));
            cpa16(s2u(&Bsm[sg * SSTG + r * GST + (chnk << 2)]),
                  B + ((size_t)(n0 + r) << 10) + 32 * sg + (chnk << 3));
        }
        CP_COMMIT();
    }

    int st = 0;
    for (int kb = 0; kb < 1024; kb += 32) {
        if (kb == 1024 - 32) { CP_WAIT(0); } else { CP_WAIT(1); }
        __syncthreads();

        if (kb + 64 < 1024) {
            int stp = st + 2; if (stp >= 3) stp -= 3;
#pragma unroll
            for (int j = 0; j < 4; j++) {
                int r = lr + (j << 5);
                cpa16(s2u(&Asm[stp * SSTG + r * GST + (chnk << 2)]),
                      A + ((size_t)(m0 + r) << 10) + kb + 64 + (chnk << 3));
                cpa16(s2u(&Bsm[stp * SSTG + r * GST + (chnk << 2)]),
                      B + ((size_t)(n0 + r) << 10) + kb + 64 + (chnk << 3));
            }
            CP_COMMIT();
        }

        const __half2* As = Asm + st * SSTG;
        const __half2* Bs = Bsm + st * SSTG;
#pragma unroll
        for (int kc = 0; kc < 2; kc++) {
            unsigned aF[4][4], bF[4][4];
#pragma unroll
            for (int mt = 0; mt < 4; mt++)
                ldsm4(aF[mt], s2u(&As[(wm + 16 * mt + arow) * GST + 8 * kc + acol]));
#pragma unroll
            for (int np = 0; np < 4; np++)
                ldsm4(bF[np], s2u(&Bs[(wn + 16 * np + brow) * GST + 8 * kc + bcol]));
#pragma unroll
            for (int mt = 0; mt < 4; mt++)
#pragma unroll
                for (int np = 0; np < 4; np++) {
                    mma16(acc[mt][2 * np],     aF[mt], bF[np][0], bF[np][1]);
                    mma16(acc[mt][2 * np + 1], aF[mt], bF[np][2], bF[np][3]);
                }
        }
        st++; if (st >= 3) st -= 3;
    }

#pragma unroll
    for (int nt = 0; nt < 8; nt++) {
        int n = n0 + wn + nt * 8 + 2 * t;
        float bv0 = bias[n], bv1 = bias[n + 1];
#pragma unroll
        for (int mt = 0; mt < 4; mt++) {
            int r = m0 + wm + mt * 16 + g;
            if (mode == 0) {
                *(float2*)&Cf[(size_t)r * 1024 + n]
                    = make_float2(acc[mt][nt][0] + bv0, acc[mt][nt][1] + bv1);
                *(float2*)&Cf[(size_t)(r + 8) * 1024 + n]
                    = make_float2(acc[mt][nt][2] + bv0, acc[mt][nt][3] + bv1);
            } else {
                int h = n >> 6, d = n & 63;
                int bb = r >> 10, tq = r & 1023;
                *(__half2*)&H[(size_t)((bb * NH + h) * TT + tq) * DH + d]
                    = pack2(acc[mt][nt][0] + bv0, acc[mt][nt][1] + bv1);
                *(__half2*)&H[(size_t)((bb * NH + h) * TT + tq + 8) * DH + d]
                    = pack2(acc[mt][nt][2] + bv0, acc[mt][nt][3] + bv1);
            }
        }
    }
}

// ---------------------------------------------------------------------------
// Flash attention, fp16 MMA (fp32 accum). BM=128, BN=64, Dh=64.
// 256 thr / 8 warps; warp w owns rows [16w,16w+16) -> quad-local softmax.
// cp.async 2-stage K/V; ldmatrix frags; P in registers.
// Mask tile (g_am8) loads ARE the S-accumulator init -> overlapped with QK mma.
// ---------------------------------------------------------------------------
#define FST 36
#define QH2  (128 * FST)
#define KVH2 (64 * FST)
#define FLASH_SMEM ((QH2 + 4 * KVH2) * 4)   // 55296 B

__global__ __launch_bounds__(256, 2)
void flash_fp16(const unsigned char* __restrict__ kpm)
{
    extern __shared__ __half2 smh[];
    __half2* Qs = smh;

    const int tid  = threadIdx.x;
    const int lane = tid & 31, wid = tid >> 5;
    const int g = lane >> 2, t = lane & 3;
    const int bh = blockIdx.x, b = bh >> 4, h = bh & 15;
    const int m0 = blockIdx.y * 128;

    const __half* Qg = g_qh + ((size_t)bh * TT + m0) * DH;
    const __half* Kg = g_kh + (size_t)bh * TT * DH;
    const __half* Vg = g_vh + (size_t)bh * TT * DH;

    const int arow = (lane & 7) + ((lane >> 3) & 1) * 8, acol = (lane >> 4) * 4;
    const int brow = (lane & 7) + (lane >> 4) * 8,       bcol = ((lane >> 3) & 1) * 4;

    // ---- prologue: Q + K/V stage 0 via cp.async ----
#pragma unroll
    for (int j = 0; j < 4; j++) {
        int c = tid + 256 * j;
        int row = c >> 3, ch = c & 7;
        cpa16(s2u(Qs + row * FST + 4 * ch), Qg + row * 64 + 8 * ch);
    }
    {
        __half2* Kp = smh + QH2;
        __half2* Vp = Kp + KVH2;
#pragma unroll
        for (int j = 0; j < 2; j++) {
            int c = tid + 256 * j;
            int row = c >> 3, ch = c & 7;
            cpa16(s2u(Kp + row * FST + 4 * ch), Kg + row * 64 + 8 * ch);
            cpa16(s2u(Vp + row * FST + 4 * ch), Vg + row * 64 + 8 * ch);
        }
    }
    CP_COMMIT();

    float o[8][4];
#pragma unroll
    for (int dt = 0; dt < 8; dt++)
#pragma unroll
        for (int c = 0; c < 4; c++) o[dt][c] = 0.f;

    float mr0 = -1e30f, mr1 = -1e30f, l0 = 0.f, l1 = 0.f;
    const int   R   = wid * 16;
    const int   tq0 = m0 + R + g;
    const float SC2 = 0.125f * LOG2E;

    const float* am0 = g_am8 + (size_t)tq0 * TT;
    const float* am8 = am0 + 8 * TT;

    unsigned aQ[4][4];
    int st = 0;

    for (int n0k = 0; n0k < TT; n0k += 64) {
        if (n0k + 64 < TT) {
            __half2* Kp = smh + QH2 + (st ^ 1) * 2 * KVH2;
            __half2* Vp = Kp + KVH2;
            const __half* Kn = Kg + (size_t)(n0k + 64) * 64;
            const __half* Vn = Vg + (size_t)(n0k + 64) * 64;
#pragma unroll
            for (int j = 0; j < 2; j++) {
                int c = tid + 256 * j;
                int row = c >> 3, ch = c & 7;
                cpa16(s2u(Kp + row * FST + 4 * ch), Kn + row * 64 + 8 * ch);
                cpa16(s2u(Vp + row * FST + 4 * ch), Vn + row * 64 + 8 * ch);
            }
            CP_COMMIT();
            CP_WAIT(1);
        } else {
            CP_WAIT(0);
        }
        __syncthreads();

        __half2* Ksp = smh + QH2 + st * 2 * KVH2;
        __half2* Vsp = Ksp + KVH2;

        if (n0k == 0) {
#pragma unroll
            for (int kc = 0; kc < 4; kc++)
                ldsm4(aQ[kc], s2u(Qs + (R + arow) * FST + 8 * kc + acol));
        }

        // warp-uniform padding-mask check for this 64-key tile
        unsigned long long kw = 0;
        if (lane < 8)
            kw = *(const unsigned long long*)(kpm + (b << 10) + n0k + (lane << 3));
        const bool anymask = __any_sync(0xffffffffu, kw != 0ull);

        // ---- S init = mask tile (am*8); QK mma accumulates on top ----
        float s[8][4];
#pragma unroll
        for (int nt = 0; nt < 8; nt++) {
            int col = n0k + nt * 8 + 2 * t;
            *(float2*)&s[nt][0] = *(const float2*)(am0 + col);
            *(float2*)&s[nt][2] = *(const float2*)(am8 + col);
        }

#pragma unroll
        for (int kc = 0; kc < 4; kc++) {
#pragma unroll
            for (int np = 0; np < 4; np++) {
                unsigned bK[4];
                ldsm4(bK, s2u(Ksp + (16 * np + brow) * FST + 8 * kc + bcol));
                mma16(s[2 * np],     aQ[kc], bK[0], bK[1]);
                mma16(s[2 * np + 1], aQ[kc], bK[2], bK[3]);
            }
        }

        // ---- online softmax (raw-domain max, scale folded into exp arg) ----
        float mx0 = -1e30f, mx1 = -1e30f;
#pragma unroll
        for (int nt = 0; nt < 8; nt++) {
            mx0 = fmaxf(mx0, fmaxf(s[nt][0], s[nt][1]));
            mx1 = fmaxf(mx1, fmaxf(s[nt][2], s[nt][3]));
        }
        mx0 = fmaxf(mx0, __shfl_xor_sync(0xffffffffu, mx0, 1));
        mx0 = fmaxf(mx0, __shfl_xor_sync(0xffffffffu, mx0, 2));
        mx1 = fmaxf(mx1, __shfl_xor_sync(0xffffffffu, mx1, 1));
        mx1 = fmaxf(mx1, __shfl_xor_sync(0xffffffffu, mx1, 2));

        float mn0 = fmaxf(mr0, mx0 * SC2), mn1 = fmaxf(mr1, mx1 * SC2);
        float al0 = exp2_fast(mr0 - mn0), al1 = exp2_fast(mr1 - mn1);
        mr0 = mn0; mr1 = mn1;

        float rs0 = 0.f, rs1 = 0.f;
        if (!anymask) {
#pragma unroll
            for (int nt = 0; nt < 8; nt++) {
                s[nt][0] = exp2_fast(fmaf(s[nt][0], SC2, -mn0));
                s[nt][1] = exp2_fast(fmaf(s[nt][1], SC2, -mn0));
                s[nt][2] = exp2_fast(fmaf(s[nt][2], SC2, -mn1));
                s[nt][3] = exp2_fast(fmaf(s[nt][3], SC2, -mn1));
                rs0 += s[nt][0] + s[nt][1];
                rs1 += s[nt][2] + s[nt][3];
            }
        } else {
#pragma unroll
            for (int nt = 0; nt < 8; nt++) {
                s[nt][0] = exp2_fast(fmaf(s[nt][0], SC2, -mn0));
                s[nt][1] = exp2_fast(fmaf(s[nt][1], SC2, -mn0));
                s[nt][2] = exp2_fast(fmaf(s[nt][2], SC2, -mn1));
                s[nt][3] = exp2_fast(fmaf(s[nt][3], SC2, -mn1));
                const unsigned char* kp = kpm + (b << 10) + n0k + (nt << 3) + (t << 1);
                if (kp[0]) { s[nt][0] = 0.f; s[nt][2] = 0.f; }
                if (kp[1]) { s[nt][1] = 0.f; s[nt][3] = 0.f; }
                rs0 += s[nt][0] + s[nt][1];
                rs1 += s[nt][2] + s[nt][3];
            }
        }
        rs0 += __shfl_xor_sync(0xffffffffu, rs0, 1);
        rs0 += __shfl_xor_sync(0xffffffffu, rs0, 2);
        rs1 += __shfl_xor_sync(0xffffffffu, rs1, 1);
        rs1 += __shfl_xor_sync(0xffffffffu, rs1, 2);
        l0 = l0 * al0 + rs0;
        l1 = l1 * al1 + rs1;

        if (!__all_sync(0xffffffffu, (al0 == 1.0f) & (al1 == 1.0f))) {
#pragma unroll
            for (int dt = 0; dt < 8; dt++) {
                o[dt][0] *= al0; o[dt][1] *= al0;
                o[dt][2] *= al1; o[dt][3] *= al1;
            }
        }

        // ---- O += P @ V  (P from registers) ----
#pragma unroll
        for (int kc = 0; kc < 4; kc++) {
            unsigned aP[4];
            aP[0] = h2u(pack2(s[2 * kc][0],     s[2 * kc][1]));
            aP[1] = h2u(pack2(s[2 * kc][2],     s[2 * kc][3]));
            aP[2] = h2u(pack2(s[2 * kc + 1][0], s[2 * kc + 1][1]));
            aP[3] = h2u(pack2(s[2 * kc + 1][2], s[2 * kc + 1][3]));
#pragma unroll
            for (int dp = 0; dp < 4; dp++) {
                unsigned bV[4];
                ldsm4t(bV, s2u(Vsp + (16 * kc + arow) * FST + 8 * dp + acol));
                mma16(o[2 * dp],     aP, bV[0], bV[1]);
                mma16(o[2 * dp + 1], aP, bV[2], bV[3]);
            }
        }
        __syncthreads();
        st ^= 1;
    }

    // ---- normalize + write fp16 [b, t, h*64+d] ----
    float inv0 = 1.f / l0, inv1 = 1.f / l1;
#pragma unroll
    for (int dt = 0; dt < 8; dt++) {
        int col = h * 64 + dt * 8 + 2 * t;
        *(__half2*)&g_ao16[(size_t)(b * TT + tq0) * EMB + col]
            = pack2(o[dt][0] * inv0, o[dt][1] * inv0);
        *(__half2*)&g_ao16[(size_t)(b * TT + tq0 + 8) * EMB + col]
            = pack2(o[dt][2] * inv1, o[dt][3] * inv1);
    }
}

// ============================================================================
extern "C" void kernel_launch(void* const* d_in, const int* in_sizes, int n_in,
                              void* d_out, int out_size)
{
    (void)in_sizes; (void)n_in; (void)out_size;
    const float*         query = (const float*)d_in[0];
    const float*         key   = (const float*)d_in[1];
    const float*         value = (const float*)d_in[2];
    const unsigned char* kpm   = (const unsigned char*)d_in[3];
    const float*         amask = (const float*)d_in[4];
    const float*         win   = (const float*)d_in[5];
    const float*         bin   = (const float*)d_in[6];
    const float*         wout  = (const float*)d_in[7];
    const float*         bout  = (const float*)d_in[8];
    float*               out   = (float*)d_out;

    __half *pq16, *pk16, *pv16, *pw16, *pwo16, *pqh, *pkh, *pvh, *pao16;
    cudaGetSymbolAddress((void**)&pq16,  g_q16);
    cudaGetSymbolAddress((void**)&pk16,  g_k16);
    cudaGetSymbolAddress((void**)&pv16,  g_v16);
    cudaGetSymbolAddress((void**)&pw16,  g_w16);
    cudaGetSymbolAddress((void**)&pwo16, g_wo16);
    cudaGetSymbolAddress((void**)&pqh,   g_qh);
    cudaGetSymbolAddress((void**)&pkh,   g_kh);
    cudaGetSymbolAddress((void**)&pvh,   g_vh);
    cudaGetSymbolAddress((void**)&pao16, g_ao16);

    // ---- fused prep (one launch) ----
    prep_all<<<dim3(4096, 6), 256>>>(query, key, value, win, wout, amask,
                                     pq16, pk16, pv16, pw16, pwo16);

    // ---- Q/K/V projections (one launch, grid.z = 3), 64x64 warp tile ----
    cudaFuncSetAttribute(gemm_fp16,
                         cudaFuncAttributeMaxDynamicSharedMemorySize, GSMEM);
    gemm_fp16<<<dim3(8, 64, 3), 128, GSMEM>>>(pq16, pk16, pv16, pw16, bin,
                                              pqh, pkh, pvh, nullptr, 1);

    // ---- flash attention ----
    cudaFuncSetAttribute(flash_fp16,
                         cudaFuncAttributeMaxDynamicSharedMemorySize, FLASH_SMEM);
    flash_fp16<<<dim3(BHD, TT / 128), 256, FLASH_SMEM>>>(kpm);

    // ---- output projection -> d_out (fp32) ----
    gemm_fp16<<<dim3(8, 64, 1), 128, GSMEM>>>(pao16, pao16, pao16, pwo16, bout,
                                              nullptr, nullptr, nullptr, out, 0);
}

// round 17
// speedup vs baseline: 2.6951x; 1.0213x over previous
#include <cuda_runtime.h>
#include <cuda_fp16.h>
#include <stdint.h>
#include <math.h>

// Problem constants
#define BQ    8
#define TT    1024
#define EMB   1024
#define NH    16
#define DH    64
#define NTOK  (BQ*TT)      // 8192
#define BHD   (BQ*NH)      // 128

#define LOG2E 1.4426950408889634f

// -------- scratch (static device arrays: no allocation APIs allowed) --------
__device__ __half g_q16 [NTOK*EMB];
__device__ __half g_k16 [NTOK*EMB];
__device__ __half g_v16 [NTOK*EMB];
__device__ __half g_w16 [3*EMB*EMB];
__device__ __half g_wo16[EMB*EMB];
__device__ __half g_qh  [BHD*TT*DH];
__device__ __half g_kh  [BHD*TT*DH];
__device__ __half g_vh  [BHD*TT*DH];
__device__ __half g_ao16[NTOK*EMB];
__device__ float  g_am8 [TT*TT];        // amask * 8  (so (QK + am8)*SC2 = base-2 score)

// ---------------------------------------------------------------------------
// helpers
// ---------------------------------------------------------------------------
__device__ __forceinline__ unsigned h2u(__half2 h) { return *(unsigned*)&h; }
__device__ __forceinline__ __half2 pack2(float x, float y) { return __floats2half2_rn(x, y); }

__device__ __forceinline__ void mma16(float* d, const unsigned* a, unsigned b0, unsigned b1) {
    asm volatile(
        "mma.sync.aligned.m16n8k16.row.col.f32.f16.f16.f32 "
        "{%0,%1,%2,%3}, {%4,%5,%6,%7}, {%8,%9}, {%0,%1,%2,%3};\n"
        : "+f"(d[0]), "+f"(d[1]), "+f"(d[2]), "+f"(d[3])
        : "r"(a[0]), "r"(a[1]), "r"(a[2]), "r"(a[3]), "r"(b0), "r"(b1));
}

__device__ __forceinline__ uint32_t s2u(const void* p) {
    return (uint32_t)__cvta_generic_to_shared(p);
}
__device__ __forceinline__ void ldsm4(unsigned* r, uint32_t addr) {
    asm volatile("ldmatrix.sync.aligned.m8n8.x4.shared.b16 {%0,%1,%2,%3}, [%4];"
                 : "=r"(r[0]), "=r"(r[1]), "=r"(r[2]), "=r"(r[3]) : "r"(addr));
}
__device__ __forceinline__ void ldsm4t(unsigned* r, uint32_t addr) {
    asm volatile("ldmatrix.sync.aligned.m8n8.x4.trans.shared.b16 {%0,%1,%2,%3}, [%4];"
                 : "=r"(r[0]), "=r"(r[1]), "=r"(r[2]), "=r"(r[3]) : "r"(addr));
}
__device__ __forceinline__ void cpa16(uint32_t dst, const void* src) {
    asm volatile("cp.async.ca.shared.global [%0], [%1], 16;" :: "r"(dst), "l"(src));
}
#define CP_COMMIT() asm volatile("cp.async.commit_group;")
#define CP_WAIT(n)  asm volatile("cp.async.wait_group %0;" :: "n"(n))

// Fast exp2, NO clamp: valid for y in (-126, 0]. 7 FMA-pipe ops + 2 ALU ops.
// r's low bits = round(y); f = frac in [-0.5,0.5]; deg-4 Taylor (rem ~4e-5);
// scale by 2^n via integer add of (bits(r)<<23) -- exact for p in [0.7,1.42).
__device__ __forceinline__ float exp2n(float y) {
    float r = y + 12582912.0f;
    float f = y - (r - 12582912.0f);
    float p =             9.6181291e-3f;
    p = fmaf(p, f,        5.5504110e-2f);
    p = fmaf(p, f,        2.4022651e-1f);
    p = fmaf(p, f,        6.9314718e-1f);
    p = fmaf(p, f,        1.0f);
    return __int_as_float(__float_as_int(p) + (__float_as_int(r) << 23));
}
// Clamped variant (for alpha, where the -1e30 init sentinel can appear).
__device__ __forceinline__ float exp2c(float y) {
    return exp2n(fmaxf(y, -120.0f));
}

// ---------------------------------------------------------------------------
// fused prep: fp32->fp16 for 5 tensors (grid.y = 0..4), mask*8 (grid.y = 5)
// ---------------------------------------------------------------------------
__global__ void prep_all(const float* __restrict__ q, const float* __restrict__ k,
                         const float* __restrict__ v, const float* __restrict__ win,
                         const float* __restrict__ wout, const float* __restrict__ am,
                         __half* __restrict__ q16, __half* __restrict__ k16,
                         __half* __restrict__ v16, __half* __restrict__ w16,
                         __half* __restrict__ wo16)
{
    int r = blockIdx.y, bx = blockIdx.x;
    if (r == 5) {
        if (bx >= TT*TT/1024) return;
        int i = (bx * 256 + threadIdx.x) * 4;
        float4 m = *(const float4*)(am + i);
        m.x *= 8.f; m.y *= 8.f; m.z *= 8.f; m.w *= 8.f;
        *(float4*)&g_am8[i] = m;
        return;
    }
    const float* src; __half* dst; int nb;
    switch (r) {
        case 0: src = q;    dst = q16;  nb = NTOK*EMB/2048;  break;
        case 1: src = k;    dst = k16;  nb = NTOK*EMB/2048;  break;
        case 2: src = v;    dst = v16;  nb = NTOK*EMB/2048;  break;
        case 3: src = win;  dst = w16;  nb = 3*EMB*EMB/2048; break;
        default: src = wout; dst = wo16; nb = EMB*EMB/2048;  break;
    }
    if (bx >= nb) return;
    int i = (bx * 256 + threadIdx.x) * 8;
    float4 a = *(const float4*)(src + i);
    float4 b = *(const float4*)(src + i + 4);
    __half2 h[4] = { pack2(a.x, a.y), pack2(a.z, a.w), pack2(b.x, b.y), pack2(b.z, b.w) };
    *(uint4*)(dst + i) = *(uint4*)h;
}

// ---------------------------------------------------------------------------
// fp16 GEMM (fp32 accum): C = A*B^T + bias. M=8192 N=1024 K=1024.
// 128x128 block tile, BK=32, 128 thr / 4 warps, warp tile 64x64,
// cp.async 3-stage, ldmatrix. LDSM/MMA = 0.25.
// ---------------------------------------------------------------------------
#define GST  20
#define SSTG (128 * GST)                 // half2 per stage per matrix
#define GSMEM (6 * SSTG * 4)             // 61440 B (3 stages x A,B)

__global__ __launch_bounds__(128, 2)
void gemm_fp16(const __half* __restrict__ A0, const __half* __restrict__ A1,
               const __half* __restrict__ A2, const __half* __restrict__ Bw,
               const float* __restrict__ bias0,
               __half* __restrict__ H0, __half* __restrict__ H1, __half* __restrict__ H2,
               float* __restrict__ Cf, int mode)
{
    extern __shared__ __half2 gsm[];
    __half2* Asm = gsm;                  // 3 stages
    __half2* Bsm = gsm + 3 * SSTG;

    const int z = blockIdx.z;
    const __half* A    = (z == 0) ? A0 : (z == 1) ? A1 : A2;
    const __half* B    = Bw + (size_t)z * 1024 * 1024;
    const float*  bias = bias0 + z * 1024;
    __half*       H    = (z == 0) ? H0 : (z == 1) ? H1 : H2;

    const int tid  = threadIdx.x;
    const int lane = tid & 31, wid = tid >> 5;      // 4 warps
    const int g = lane >> 2, t = lane & 3;
    const int wm = (wid >> 1) * 64, wn = (wid & 1) * 64;
    const int m0 = blockIdx.y * 128, n0 = blockIdx.x * 128;

    const int rpat = (lane >> 3) + (((lane >> 2) & 1) << 2);   // 0,4,1,5,2,6,3,7
    const int chnk = lane & 3;
    const int lr   = (wid << 3) + rpat;                         // rows 0..31

    const int arow = (lane & 7) + ((lane >> 3) & 1) * 8, acol = (lane >> 4) * 4;
    const int brow = (lane & 7) + (lane >> 4) * 8,       bcol = ((lane >> 3) & 1) * 4;

    float acc[4][8][4];
#pragma unroll
    for (int mt = 0; mt < 4; mt++)
#pragma unroll
        for (int nt = 0; nt < 8; nt++)
#pragma unroll
            for (int c = 0; c < 4; c++) acc[mt][nt][c] = 0.f;

    // prologue: stages 0 (kb=0) and 1 (kb=32)
#pragma unroll
    for (int sg = 0; sg < 2; sg++) {
#pragma unroll
        for (int j = 0; j < 4; j++) {
            int r = lr + (j << 5);
            cpa16(s2u(&Asm[sg * SSTG + r * GST + (chnk << 2)]),
                  A + ((size_t)(m0 + r) << 10) + 32 * sg + (chnk << 3));
            cpa16(s2u(&Bsm[sg * SSTG + r * GST + (chnk << 2)]),
                  B + ((size_t)(n0 + r) << 10) + 32 * sg + (chnk << 3));
        }
        CP_COMMIT();
    }

    int st = 0;
    for (int kb = 0; kb < 1024; kb += 32) {
        if (kb == 1024 - 32) { CP_WAIT(0); } else { CP_WAIT(1); }
        __syncthreads();

        if (kb + 64 < 1024) {
            int stp = st + 2; if (stp >= 3) stp -= 3;
#pragma unroll
            for (int j = 0; j < 4; j++) {
                int r = lr + (j << 5);
                cpa16(s2u(&Asm[stp * SSTG + r * GST + (chnk << 2)]),
                      A + ((size_t)(m0 + r) << 10) + kb + 64 + (chnk << 3));
                cpa16(s2u(&Bsm[stp * SSTG + r * GST + (chnk << 2)]),
                      B + ((size_t)(n0 + r) << 10) + kb + 64 + (chnk << 3));
            }
            CP_COMMIT();
        }

        const __half2* As = Asm + st * SSTG;
        const __half2* Bs = Bsm + st * SSTG;
#pragma unroll
        for (int kc = 0; kc < 2; kc++) {
            unsigned aF[4][4], bF[4][4];
#pragma unroll
            for (int mt = 0; mt < 4; mt++)
                ldsm4(aF[mt], s2u(&As[(wm + 16 * mt + arow) * GST + 8 * kc + acol]));
#pragma unroll
            for (int np = 0; np < 4; np++)
                ldsm4(bF[np], s2u(&Bs[(wn + 16 * np + brow) * GST + 8 * kc + bcol]));
#pragma unroll
            for (int mt = 0; mt < 4; mt++)
#pragma unroll
                for (int np = 0; np < 4; np++) {
                    mma16(acc[mt][2 * np],     aF[mt], bF[np][0], bF[np][1]);
                    mma16(acc[mt][2 * np + 1], aF[mt], bF[np][2], bF[np][3]);
                }
        }
        st++; if (st >= 3) st -= 3;
    }

#pragma unroll
    for (int nt = 0; nt < 8; nt++) {
        int n = n0 + wn + nt * 8 + 2 * t;
        float bv0 = bias[n], bv1 = bias[n + 1];
#pragma unroll
        for (int mt = 0; mt < 4; mt++) {
            int r = m0 + wm + mt * 16 + g;
            if (mode == 0) {
                *(float2*)&Cf[(size_t)r * 1024 + n]
                    = make_float2(acc[mt][nt][0] + bv0, acc[mt][nt][1] + bv1);
                *(float2*)&Cf[(size_t)(r + 8) * 1024 + n]
                    = make_float2(acc[mt][nt][2] + bv0, acc[mt][nt][3] + bv1);
            } else {
                int h = n >> 6, d = n & 63;
                int bb = r >> 10, tq = r & 1023;
                *(__half2*)&H[(size_t)((bb * NH + h) * TT + tq) * DH + d]
                    = pack2(acc[mt][nt][0] + bv0, acc[mt][nt][1] + bv1);
                *(__half2*)&H[(size_t)((bb * NH + h) * TT + tq + 8) * DH + d]
                    = pack2(acc[mt][nt][2] + bv0, acc[mt][nt][3] + bv1);
            }
        }
    }
}

// ---------------------------------------------------------------------------
// Flash attention, fp16 MMA (fp32 accum). BM=128, BN=64, Dh=64.
// 256 thr / 8 warps; warp w owns rows [16w,16w+16) -> quad-local softmax.
// cp.async 2-stage K/V; ldmatrix frags; P in registers.
// Mask tile (g_am8) loads ARE the S-accumulator init.
// exp2n: 7 FMA-pipe ops, no clamp (args bounded; sentinel only reaches exp2c).
// ---------------------------------------------------------------------------
#define FST 36
#define QH2  (128 * FST)
#define KVH2 (64 * FST)
#define FLASH_SMEM ((QH2 + 4 * KVH2) * 4)   // 55296 B

__global__ __launch_bounds__(256, 2)
void flash_fp16(const unsigned char* __restrict__ kpm)
{
    extern __shared__ __half2 smh[];
    __half2* Qs = smh;

    const int tid  = threadIdx.x;
    const int lane = tid & 31, wid = tid >> 5;
    const int g = lane >> 2, t = lane & 3;
    const int bh = blockIdx.x, b = bh >> 4, h = bh & 15;
    const int m0 = blockIdx.y * 128;

    const __half* Qg = g_qh + ((size_t)bh * TT + m0) * DH;
    const __half* Kg = g_kh + (size_t)bh * TT * DH;
    const __half* Vg = g_vh + (size_t)bh * TT * DH;

    const int arow = (lane & 7) + ((lane >> 3) & 1) * 8, acol = (lane >> 4) * 4;
    const int brow = (lane & 7) + (lane >> 4) * 8,       bcol = ((lane >> 3) & 1) * 4;

    // ---- prologue: Q + K/V stage 0 via cp.async ----
#pragma unroll
    for (int j = 0; j < 4; j++) {
        int c = tid + 256 * j;
        int row = c >> 3, ch = c & 7;
        cpa16(s2u(Qs + row * FST + 4 * ch), Qg + row * 64 + 8 * ch);
    }
    {
        __half2* Kp = smh + QH2;
        __half2* Vp = Kp + KVH2;
#pragma unroll
        for (int j = 0; j < 2; j++) {
            int c = tid + 256 * j;
            int row = c >> 3, ch = c & 7;
            cpa16(s2u(Kp + row * FST + 4 * ch), Kg + row * 64 + 8 * ch);
            cpa16(s2u(Vp + row * FST + 4 * ch), Vg + row * 64 + 8 * ch);
        }
    }
    CP_COMMIT();

    float o[8][4];
#pragma unroll
    for (int dt = 0; dt < 8; dt++)
#pragma unroll
        for (int c = 0; c < 4; c++) o[dt][c] = 0.f;

    float mr0 = -1e30f, mr1 = -1e30f, l0 = 0.f, l1 = 0.f;
    const int   R   = wid * 16;
    const int   tq0 = m0 + R + g;
    const float SC2 = 0.125f * LOG2E;

    const float* am0 = g_am8 + (size_t)tq0 * TT;
    const float* am8 = am0 + 8 * TT;

    unsigned aQ[4][4];
    int st = 0;

    for (int n0k = 0; n0k < TT; n0k += 64) {
        if (n0k + 64 < TT) {
            __half2* Kp = smh + QH2 + (st ^ 1) * 2 * KVH2;
            __half2* Vp = Kp + KVH2;
            const __half* Kn = Kg + (size_t)(n0k + 64) * 64;
            const __half* Vn = Vg + (size_t)(n0k + 64) * 64;
#pragma unroll
            for (int j = 0; j < 2; j++) {
                int c = tid + 256 * j;
                int row = c >> 3, ch = c & 7;
                cpa16(s2u(Kp + row * FST + 4 * ch), Kn + row * 64 + 8 * ch);
                cpa16(s2u(Vp + row * FST + 4 * ch), Vn + row * 64 + 8 * ch);
            }
            CP_COMMIT();
            CP_WAIT(1);
        } else {
            CP_WAIT(0);
        }
        __syncthreads();

        __half2* Ksp = smh + QH2 + st * 2 * KVH2;
        __half2* Vsp = Ksp + KVH2;

        if (n0k == 0) {
#pragma unroll
            for (int kc = 0; kc < 4; kc++)
                ldsm4(aQ[kc], s2u(Qs + (R + arow) * FST + 8 * kc + acol));
        }

        // warp-uniform padding-mask check for this 64-key tile
        unsigned long long kw = 0;
        if (lane < 8)
            kw = *(const unsigned long long*)(kpm + (b << 10) + n0k + (lane << 3));
        const bool anymask = __any_sync(0xffffffffu, kw != 0ull);

        // ---- S init = mask tile (am*8); QK mma accumulates on top ----
        float s[8][4];
#pragma unroll
        for (int nt = 0; nt < 8; nt++) {
            int col = n0k + nt * 8 + 2 * t;
            *(float2*)&s[nt][0] = *(const float2*)(am0 + col);
            *(float2*)&s[nt][2] = *(const float2*)(am8 + col);
        }

#pragma unroll
        for (int kc = 0; kc < 4; kc++) {
#pragma unroll
            for (int np = 0; np < 4; np++) {
                unsigned bK[4];
                ldsm4(bK, s2u(Ksp + (16 * np + brow) * FST + 8 * kc + bcol));
                mma16(s[2 * np],     aQ[kc], bK[0], bK[1]);
                mma16(s[2 * np + 1], aQ[kc], bK[2], bK[3]);
            }
        }

        // ---- online softmax (raw-domain max, scale folded into exp arg) ----
        float mx0 = -1e30f, mx1 = -1e30f;
#pragma unroll
        for (int nt = 0; nt < 8; nt++) {
            mx0 = fmaxf(mx0, fmaxf(s[nt][0], s[nt][1]));
            mx1 = fmaxf(mx1, fmaxf(s[nt][2], s[nt][3]));
        }
        mx0 = fmaxf(mx0, __shfl_xor_sync(0xffffffffu, mx0, 1));
        mx0 = fmaxf(mx0, __shfl_xor_sync(0xffffffffu, mx0, 2));
        mx1 = fmaxf(mx1, __shfl_xor_sync(0xffffffffu, mx1, 1));
        mx1 = fmaxf(mx1, __shfl_xor_sync(0xffffffffu, mx1, 2));

        float mn0 = fmaxf(mr0, mx0 * SC2), mn1 = fmaxf(mr1, mx1 * SC2);
        float al0 = exp2c(mr0 - mn0), al1 = exp2c(mr1 - mn1);
        mr0 = mn0; mr1 = mn1;

        float rs0 = 0.f, rs1 = 0.f;
        if (!anymask) {
#pragma unroll
            for (int nt = 0; nt < 8; nt++) {
                s[nt][0] = exp2n(fmaf(s[nt][0], SC2, -mn0));
                s[nt][1] = exp2n(fmaf(s[nt][1], SC2, -mn0));
                s[nt][2] = exp2n(fmaf(s[nt][2], SC2, -mn1));
                s[nt][3] = exp2n(fmaf(s[nt][3], SC2, -mn1));
                rs0 += s[nt][0] + s[nt][1];
                rs1 += s[nt][2] + s[nt][3];
            }
        } else {
#pragma unroll
            for (int nt = 0; nt < 8; nt++) {
                s[nt][0] = exp2n(fmaf(s[nt][0], SC2, -mn0));
                s[nt][1] = exp2n(fmaf(s[nt][1], SC2, -mn0));
                s[nt][2] = exp2n(fmaf(s[nt][2], SC2, -mn1));
                s[nt][3] = exp2n(fmaf(s[nt][3], SC2, -mn1));
                const unsigned char* kp = kpm + (b << 10) + n0k + (nt << 3) + (t << 1);
                if (kp[0]) { s[nt][0] = 0.f; s[nt][2] = 0.f; }
                if (kp[1]) { s[nt][1] = 0.f; s[nt][3] = 0.f; }
                rs0 += s[nt][0] + s[nt][1];
                rs1 += s[nt][2] + s[nt][3];
            }
        }
        rs0 += __shfl_xor_sync(0xffffffffu, rs0, 1);
        rs0 += __shfl_xor_sync(0xffffffffu, rs0, 2);
        rs1 += __shfl_xor_sync(0xffffffffu, rs1, 1);
        rs1 += __shfl_xor_sync(0xffffffffu, rs1, 2);
        l0 = l0 * al0 + rs0;
        l1 = l1 * al1 + rs1;

        if (!__all_sync(0xffffffffu, (al0 == 1.0f) & (al1 == 1.0f))) {
#pragma unroll
            for (int dt = 0; dt < 8; dt++) {
                o[dt][0] *= al0; o[dt][1] *= al0;
                o[dt][2] *= al1; o[dt][3] *= al1;
            }
        }

        // ---- O += P @ V  (P from registers) ----
#pragma unroll
        for (int kc = 0; kc < 4; kc++) {
            unsigned aP[4];
            aP[0] = h2u(pack2(s[2 * kc][0],     s[2 * kc][1]));
            aP[1] = h2u(pack2(s[2 * kc][2],     s[2 * kc][3]));
            aP[2] = h2u(pack2(s[2 * kc + 1][0], s[2 * kc + 1][1]));
            aP[3] = h2u(pack2(s[2 * kc + 1][2], s[2 * kc + 1][3]));
#pragma unroll
            for (int dp = 0; dp < 4; dp++) {
                unsigned bV[4];
                ldsm4t(bV, s2u(Vsp + (16 * kc + arow) * FST + 8 * dp + acol));
                mma16(o[2 * dp],     aP, bV[0], bV[1]);
                mma16(o[2 * dp + 1], aP, bV[2], bV[3]);
            }
        }
        __syncthreads();
        st ^= 1;
    }

    // ---- normalize + write fp16 [b, t, h*64+d] ----
    float inv0 = 1.f / l0, inv1 = 1.f / l1;
#pragma unroll
    for (int dt = 0; dt < 8; dt++) {
        int col = h * 64 + dt * 8 + 2 * t;
        *(__half2*)&g_ao16[(size_t)(b * TT + tq0) * EMB + col]
            = pack2(o[dt][0] * inv0, o[dt][1] * inv0);
        *(__half2*)&g_ao16[(size_t)(b * TT + tq0 + 8) * EMB + col]
            = pack2(o[dt][2] * inv1, o[dt][3] * inv1);
    }
}

// ============================================================================
extern "C" void kernel_launch(void* const* d_in, const int* in_sizes, int n_in,
                              void* d_out, int out_size)
{
    (void)in_sizes; (void)n_in; (void)out_size;
    const float*         query = (const float*)d_in[0];
    const float*         key   = (const float*)d_in[1];
    const float*         value = (const float*)d_in[2];
    const unsigned char* kpm   = (const unsigned char*)d_in[3];
    const float*         amask = (const float*)d_in[4];
    const float*         win   = (const float*)d_in[5];
    const float*         bin   = (const float*)d_in[6];
    const float*         wout  = (const float*)d_in[7];
    const float*         bout  = (const float*)d_in[8];
    float*               out   = (float*)d_out;

    __half *pq16, *pk16, *pv16, *pw16, *pwo16, *pqh, *pkh, *pvh, *pao16;
    cudaGetSymbolAddress((void**)&pq16,  g_q16);
    cudaGetSymbolAddress((void**)&pk16,  g_k16);
    cudaGetSymbolAddress((void**)&pv16,  g_v16);
    cudaGetSymbolAddress((void**)&pw16,  g_w16);
    cudaGetSymbolAddress((void**)&pwo16, g_wo16);
    cudaGetSymbolAddress((void**)&pqh,   g_qh);
    cudaGetSymbolAddress((void**)&pkh,   g_kh);
    cudaGetSymbolAddress((void**)&pvh,   g_vh);
    cudaGetSymbolAddress((void**)&pao16, g_ao16);

    // ---- fused prep (one launch) ----
    prep_all<<<dim3(4096, 6), 256>>>(query, key, value, win, wout, amask,
                                     pq16, pk16, pv16, pw16, pwo16);

    // ---- Q/K/V projections (one launch, grid.z = 3), 64x64 warp tile ----
    cudaFuncSetAttribute(gemm_fp16,
                         cudaFuncAttributeMaxDynamicSharedMemorySize, GSMEM);
    gemm_fp16<<<dim3(8, 64, 3), 128, GSMEM>>>(pq16, pk16, pv16, pw16, bin,
                                              pqh, pkh, pvh, nullptr, 1);

    // ---- flash attention ----
    cudaFuncSetAttribute(flash_fp16,
                         cudaFuncAttributeMaxDynamicSharedMemorySize, FLASH_SMEM);
    flash_fp16<<<dim3(BHD, TT / 128), 256, FLASH_SMEM>>>(kpm);

    // ---- output projection -> d_out (fp32) ----
    gemm_fp16<<<dim3(8, 64, 1), 128, GSMEM>>>(pao16, pao16, pao16, pwo16, bout,
                                              nullptr, nullptr, nullptr, out, 0);
}